// round 11
// baseline (speedup 1.0000x reference)
#include <cuda_runtime.h>
#include <cstdint>

#define Bc 2
#define Sc 2048
#define Dc 1024
#define Hc 16
#define HDc 64
#define BHc (Bc*Hc)
#define SCALEc 0.125f              // 64^-0.5
#define KLOG2 0.1803368801111243f // SCALEc * log2(e)

// ---- scratch (allocation-free rule: __device__ globals) --------------------
__device__ float g_Q[(size_t)Bc * Sc * Dc];
__device__ float g_K[(size_t)Bc * Sc * Dc];
__device__ float g_V[(size_t)Bc * Sc * Dc];
__device__ float g_ctx[(size_t)Bc * Sc * Dc];
__device__ float g_invsum[(size_t)BHc * Sc];
// pre-rounded (tf32) copies of inputs + weights
__device__ float g_qin[(size_t)Bc * Sc * Dc];
__device__ float g_kin[(size_t)Bc * Sc * Dc];
__device__ float g_vin[(size_t)Bc * Sc * Dc];
__device__ float g_wq[(size_t)Dc * Dc];
__device__ float g_wk[(size_t)Dc * Dc];
__device__ float g_wv[(size_t)Dc * Dc];
__device__ float g_wo[(size_t)Dc * Dc];
__device__ float g_attn_fb[(size_t)BHc * Sc * Sc];   // fallback if out only holds `output`

// ---- helpers ----------------------------------------------------------------
__device__ __forceinline__ float tf32_round(float x) {
    return __uint_as_float((__float_as_uint(x) + 0x1000u) & 0xFFFFE000u);
}
__device__ __forceinline__ uint32_t f2tf(float x) {
    uint32_t r; asm("cvt.rna.tf32.f32 %0, %1;" : "=r"(r) : "f"(x)); return r;
}
__device__ __forceinline__ float ex2(float x) {
    float r; asm("ex2.approx.f32 %0, %1;" : "=f"(r) : "f"(x)); return r;
}
__device__ __forceinline__ void mma8(float* d, const uint32_t* a, const uint32_t* b) {
    asm volatile(
        "mma.sync.aligned.m16n8k8.row.col.f32.tf32.tf32.f32 "
        "{%0,%1,%2,%3}, {%4,%5,%6,%7}, {%8,%9}, {%0,%1,%2,%3};\n"
        : "+f"(d[0]), "+f"(d[1]), "+f"(d[2]), "+f"(d[3])
        : "r"(a[0]), "r"(a[1]), "r"(a[2]), "r"(a[3]), "r"(b[0]), "r"(b[1]));
}
__device__ __forceinline__ uint32_t smem_u32(const void* p) {
    uint32_t r;
    asm("{ .reg .u64 t; cvta.to.shared.u64 t, %1; cvt.u32.u64 %0, t; }"
        : "=r"(r) : "l"(p));
    return r;
}
__device__ __forceinline__ void cpa16(uint32_t saddr, const void* g) {
    asm volatile("cp.async.cg.shared.global [%0], [%1], 16;" :: "r"(saddr), "l"(g));
}
__device__ __forceinline__ void cpa_commit() { asm volatile("cp.async.commit_group;"); }
__device__ __forceinline__ void cpa_wait0()  { asm volatile("cp.async.wait_group 0;"); }
__device__ __forceinline__ void cpa_wait1()  { asm volatile("cp.async.wait_group 1;"); }

// ============================================================================
// prep: round inputs + weights to tf32 (producer-side rounding).
// ============================================================================
__global__ __launch_bounds__(256)
void prep_round(const float4* __restrict__ q, const float4* __restrict__ k,
                const float4* __restrict__ v,
                const float4* __restrict__ wq, const float4* __restrict__ wk,
                const float4* __restrict__ wv, const float4* __restrict__ wo,
                float4* __restrict__ oq, float4* __restrict__ ok,
                float4* __restrict__ ov,
                float4* __restrict__ owq, float4* __restrict__ owk,
                float4* __restrict__ owv, float4* __restrict__ owo) {
    const float4* src; float4* dst; size_t n4;
    const size_t NIN = (size_t)Bc * Sc * Dc / 4;
    const size_t NW  = (size_t)Dc * Dc / 4;
    switch (blockIdx.z) {
        case 0: src = q;  dst = oq;  n4 = NIN; break;
        case 1: src = k;  dst = ok;  n4 = NIN; break;
        case 2: src = v;  dst = ov;  n4 = NIN; break;
        case 3: src = wq; dst = owq; n4 = NW;  break;
        case 4: src = wk; dst = owk; n4 = NW;  break;
        case 5: src = wv; dst = owv; n4 = NW;  break;
        default: src = wo; dst = owo; n4 = NW;  break;
    }
    size_t i = (size_t)blockIdx.x * 256 + threadIdx.x;
    const size_t stride = (size_t)gridDim.x * 256;
    for (; i < n4; i += stride) {
        float4 t = src[i];
        t.x = tf32_round(t.x); t.y = tf32_round(t.y);
        t.z = tf32_round(t.z); t.w = tf32_round(t.w);
        dst[i] = t;
    }
}

// ============================================================================
// GEMM + bias: cp.async double-buffered, BK=32, pure-truncation tf32
// fragments (operands pre-rounded, truncation == rna). Dynamic smem 70 KB.
// BM=BN=128, 256 threads = 8 warps (2m x 4n), warp tile 64x32.
// Layouts (floats): A buf s at s*4608, [128][36]; B buf s at 9216+s*4352, [32][136].
// ============================================================================
#define GA_BUF 4608
#define GB_OFF 9216
#define GB_BUF 4352
#define GSMEM_BYTES 71680

template<bool RND_OUT>
__device__ __forceinline__
void gemm_body(const float* __restrict__ A, const float* __restrict__ W,
               const float* __restrict__ bias, float* __restrict__ C,
               int M, int N, int K, float* smf) {
    const int tid = threadIdx.x;
    const int lane = tid & 31, warp = tid >> 5;
    const int wm = warp >> 2, wn = warp & 3;
    const int row0 = blockIdx.y * 128, col0 = blockIdx.x * 128;
    const int r_lo = lane >> 2, c_lo = lane & 3;

    // staging: A tile 128x32 (2 thr/row, 16 floats each); B tile 32x128 (8 thr/row)
    const int rowA = tid >> 1, colA = (tid & 1) * 16;
    const int rowB = tid >> 3, colB = (tid & 7) * 16;

    const uint32_t sbase = smem_u32(smf);
    const uint32_t sA[2] = { sbase + (uint32_t)(0 * GA_BUF + rowA * 36 + colA) * 4,
                             sbase + (uint32_t)(1 * GA_BUF + rowA * 36 + colA) * 4 };
    const uint32_t sB[2] = { sbase + (uint32_t)(GB_OFF + 0 * GB_BUF + rowB * 136 + colB) * 4,
                             sbase + (uint32_t)(GB_OFF + 1 * GB_BUF + rowB * 136 + colB) * 4 };
    const float* gA = A + (size_t)(row0 + rowA) * K + colA;
    const float* gB = W + (size_t)rowB * N + col0 + colB;

    float acc[4][4][4] = {};

#pragma unroll
    for (int i = 0; i < 4; i++) {
        cpa16(sA[0] + i * 16, gA + i * 4);
        cpa16(sB[0] + i * 16, gB + i * 4);
    }
    cpa_commit();

    const int nk = K >> 5;
    for (int kt = 0; kt < nk; kt++) {
        const int s = kt & 1;
        if (kt + 1 < nk) {
            const float* gA2 = gA + (kt + 1) * 32;
            const float* gB2 = gB + (size_t)(kt + 1) * 32 * N;
#pragma unroll
            for (int i = 0; i < 4; i++) {
                cpa16(sA[s ^ 1] + i * 16, gA2 + i * 4);
                cpa16(sB[s ^ 1] + i * 16, gB2 + i * 4);
            }
            cpa_commit();
            cpa_wait1();
        } else {
            cpa_wait0();
        }
        __syncthreads();

        const float* As_ = smf + s * GA_BUF;                 // [128][36]
        const float* Bs_ = smf + GB_OFF + s * GB_BUF;        // [32][136]
#pragma unroll
        for (int ks = 0; ks < 32; ks += 8) {
            uint32_t af[4][4], bf[4][2];
#pragma unroll
            for (int mt = 0; mt < 4; mt++) {
                int rb = wm * 64 + mt * 16 + r_lo;
                af[mt][0] = __float_as_uint(As_[rb * 36 + ks + c_lo]);
                af[mt][1] = __float_as_uint(As_[(rb + 8) * 36 + ks + c_lo]);
                af[mt][2] = __float_as_uint(As_[rb * 36 + ks + 4 + c_lo]);
                af[mt][3] = __float_as_uint(As_[(rb + 8) * 36 + ks + 4 + c_lo]);
            }
#pragma unroll
            for (int nt = 0; nt < 4; nt++) {
                int cb = wn * 32 + nt * 8 + r_lo;
                bf[nt][0] = __float_as_uint(Bs_[(ks + c_lo) * 136 + cb]);
                bf[nt][1] = __float_as_uint(Bs_[(ks + 4 + c_lo) * 136 + cb]);
            }
#pragma unroll
            for (int mt = 0; mt < 4; mt++)
#pragma unroll
                for (int nt = 0; nt < 4; nt++)
                    mma8(acc[mt][nt], af[mt], bf[nt]);
        }
        __syncthreads();
    }

#pragma unroll
    for (int mt = 0; mt < 4; mt++) {
        int row = row0 + wm * 64 + mt * 16 + r_lo;
#pragma unroll
        for (int nt = 0; nt < 4; nt++) {
            int col = col0 + wn * 32 + nt * 8 + c_lo * 2;
            float b0 = bias[col], b1 = bias[col + 1];
            float v0 = acc[mt][nt][0] + b0, v1 = acc[mt][nt][1] + b1;
            float v2 = acc[mt][nt][2] + b0, v3 = acc[mt][nt][3] + b1;
            if (RND_OUT) {
                v0 = tf32_round(v0); v1 = tf32_round(v1);
                v2 = tf32_round(v2); v3 = tf32_round(v3);
            }
            C[(size_t)row * N + col]           = v0;
            C[(size_t)row * N + col + 1]       = v1;
            C[(size_t)(row + 8) * N + col]     = v2;
            C[(size_t)(row + 8) * N + col + 1] = v3;
        }
    }
}

__global__ __launch_bounds__(256)
void gemm_bias_tc(const float* __restrict__ A, const float* __restrict__ W,
                  const float* __restrict__ bias, float* __restrict__ C,
                  int M, int N, int K) {
    extern __shared__ float gsm[];
    gemm_body<false>(A, W, bias, C, M, N, K, gsm);
}

__global__ __launch_bounds__(256)
void qkv_gemm(const float* __restrict__ q, const float* __restrict__ k,
              const float* __restrict__ v,
              const float* __restrict__ Wq, const float* __restrict__ bq,
              const float* __restrict__ Wk, const float* __restrict__ bk,
              const float* __restrict__ Wv, const float* __restrict__ bv,
              float* __restrict__ Qo, float* __restrict__ Ko, float* __restrict__ Vo) {
    extern __shared__ float gsm[];
    const float *A, *W, *bias; float* C;
    if (blockIdx.z == 0)      { A = q; W = Wq; bias = bq; C = Qo; }
    else if (blockIdx.z == 1) { A = k; W = Wk; bias = bk; C = Ko; }
    else                      { A = v; W = Wv; bias = bv; C = Vo; }
    gemm_body<true>(A, W, bias, C, Bc * Sc, Dc, Dc, gsm);
}

// ============================================================================
// Fused attention: 512 threads (16 warps, 8m x 2n), 128 q-rows/block,
// 128-key K/V tiles double-buffered. sV stride 72 (conflict-free PV frags).
// Q raw-loaded (pre-rounded tf32 bits), E regs->gmem unnormalized,
// PV via shuffle transpose, ctx rounded at write, inv -> gmem for norm_k.
// ============================================================================
#define FK0 0
#define FK1 8704
#define FV0 17408            // stride 72: 128*72 = 9216 per buffer
#define FV1 26624
#define FRED 35840
#define FRED2 36096
#define FTOT 36224           // *4 = 144896 bytes

__global__ __launch_bounds__(512)
void fused_attn(const float* __restrict__ Qp, const float* __restrict__ Kp,
                const float* __restrict__ Vp, float* __restrict__ attn,
                float* __restrict__ invg, float* __restrict__ ctx) {
    extern __shared__ float smf[];
    const uint32_t sbase = smem_u32(smf);

    const int bh = blockIdx.y, b = bh >> 4, h = bh & 15;
    const int row0 = blockIdx.x * 128;
    const float* Qh = Qp + (size_t)b * Sc * Dc + h * HDc;
    const float* Kh = Kp + (size_t)b * Sc * Dc + h * HDc;
    const float* Vh = Vp + (size_t)b * Sc * Dc + h * HDc;
    float* outp = attn + (size_t)bh * Sc * Sc;

    const int tid = threadIdx.x, lane = tid & 31, warp = tid >> 5;
    const int wm = warp >> 1, wn = warp & 1;   // 8m x 2n
    const int g = lane >> 2, c = lane & 3;

    const int ldr0 = tid >> 4;                 // rows 0..31 (+32 per i)
    const int ldc4 = (tid & 15) * 4;

    {
#pragma unroll
        for (int i = 0; i < 4; i++) {
            int r = ldr0 + i * 32;
            cpa16(sbase + (uint32_t)(FK0 + r * 68 + ldc4) * 4, Kh + (size_t)r * Dc + ldc4);
            cpa16(sbase + (uint32_t)(FV0 + r * 72 + ldc4) * 4, Vh + (size_t)r * Dc + ldc4);
        }
        cpa_commit();
    }

    // Q fragments: raw bits (Qp pre-rounded to tf32 by qkv epilogue)
    uint32_t qf[8][4];
    {
        const int qr = row0 + wm * 16;
#pragma unroll
        for (int s8 = 0; s8 < 8; s8++) {
            qf[s8][0] = __float_as_uint(Qh[(size_t)(qr + g)     * Dc + s8 * 8 + c]);
            qf[s8][1] = __float_as_uint(Qh[(size_t)(qr + g + 8) * Dc + s8 * 8 + c]);
            qf[s8][2] = __float_as_uint(Qh[(size_t)(qr + g)     * Dc + s8 * 8 + c + 4]);
            qf[s8][3] = __float_as_uint(Qh[(size_t)(qr + g + 8) * Dc + s8 * 8 + c + 4]);
        }
    }

    cpa_wait0();
    __syncthreads();

    float accU[8][4] = {};
    float rs0 = 0.f, rs1 = 0.f;

    const int src1 = (lane & ~3) | (c >> 1);
    const int src2 = src1 + 2;
    const bool odd = (c & 1);

    for (int kt = 0; kt < 16; kt++) {
        const int s = kt & 1;
        if (kt + 1 < 16) {
            const float* gk = Kh + (size_t)((kt + 1) * 128) * Dc;
            const float* gv = Vh + (size_t)((kt + 1) * 128) * Dc;
            const int KD = s ? FK0 : FK1;
            const int VD = s ? FV0 : FV1;
#pragma unroll
            for (int i = 0; i < 4; i++) {
                int r = ldr0 + i * 32;
                cpa16(sbase + (uint32_t)(KD + r * 68 + ldc4) * 4, gk + (size_t)r * Dc + ldc4);
                cpa16(sbase + (uint32_t)(VD + r * 72 + ldc4) * 4, gv + (size_t)r * Dc + ldc4);
            }
            cpa_commit();
        }
        const float* sK = smf + (s ? FK1 : FK0);
        const float* sV = smf + (s ? FV1 : FV0);
        const int k0 = kt * 128;

#pragma unroll
        for (int half = 0; half < 2; half++) {
            const int colbase = wn * 64 + half * 32;

            float accS[4][4] = {};
#pragma unroll
            for (int s8 = 0; s8 < 8; s8++) {
                uint32_t bf[4][2];
#pragma unroll
                for (int nt = 0; nt < 4; nt++) {
                    int kc = colbase + nt * 8 + g;
                    bf[nt][0] = __float_as_uint(sK[kc * 68 + s8 * 8 + c]);
                    bf[nt][1] = __float_as_uint(sK[kc * 68 + s8 * 8 + c + 4]);
                }
#pragma unroll
                for (int nt = 0; nt < 4; nt++)
                    mma8(accS[nt], qf[s8], bf[nt]);
            }

            const int grow = row0 + wm * 16 + g;
#pragma unroll
            for (int nt = 0; nt < 4; nt++) {
                float e0 = ex2(accS[nt][0] * KLOG2);
                float e1 = ex2(accS[nt][1] * KLOG2);
                float e2 = ex2(accS[nt][2] * KLOG2);
                float e3 = ex2(accS[nt][3] * KLOG2);
                rs0 += e0 + e1; rs1 += e2 + e3;
                int gcol = k0 + colbase + nt * 8 + c * 2;
                *reinterpret_cast<float2*>(&outp[(size_t)grow * Sc + gcol])       = make_float2(e0, e1);
                *reinterpret_cast<float2*>(&outp[(size_t)(grow + 8) * Sc + gcol]) = make_float2(e2, e3);
                accS[nt][0] = e0; accS[nt][1] = e1; accS[nt][2] = e2; accS[nt][3] = e3;
            }

#pragma unroll
            for (int s4 = 0; s4 < 4; s4++) {
                float x0 = __shfl_sync(0xffffffffu, accS[s4][0], src1);
                float x1 = __shfl_sync(0xffffffffu, accS[s4][1], src1);
                float y0 = __shfl_sync(0xffffffffu, accS[s4][2], src1);
                float y1 = __shfl_sync(0xffffffffu, accS[s4][3], src1);
                float z0 = __shfl_sync(0xffffffffu, accS[s4][0], src2);
                float z1 = __shfl_sync(0xffffffffu, accS[s4][1], src2);
                float w0 = __shfl_sync(0xffffffffu, accS[s4][2], src2);
                float w1 = __shfl_sync(0xffffffffu, accS[s4][3], src2);
                uint32_t af[4];
                af[0] = f2tf(odd ? x1 : x0);
                af[1] = f2tf(odd ? y1 : y0);
                af[2] = f2tf(odd ? z1 : z0);
                af[3] = f2tf(odd ? w1 : w0);
                const int vr = colbase + s4 * 8 + c;
#pragma unroll
                for (int nt = 0; nt < 8; nt++) {
                    uint32_t bf[2];
                    bf[0] = __float_as_uint(sV[vr * 72 + nt * 8 + g]);
                    bf[1] = __float_as_uint(sV[(vr + 4) * 72 + nt * 8 + g]);
                    mma8(accU[nt], af, bf);
                }
            }
        }

        if (kt + 1 < 16) cpa_wait0();
        __syncthreads();
    }

    float* red  = smf + FRED;
    float* red2 = smf + FRED2;
    {
        float v0 = rs0, v1 = rs1;
        v0 += __shfl_xor_sync(0xffffffffu, v0, 1);
        v0 += __shfl_xor_sync(0xffffffffu, v0, 2);
        v1 += __shfl_xor_sync(0xffffffffu, v1, 1);
        v1 += __shfl_xor_sync(0xffffffffu, v1, 2);
        if (c == 0) {
            red[(wm * 16 + g) * 2 + wn]     = v0;
            red[(wm * 16 + g + 8) * 2 + wn] = v1;
        }
    }
    __syncthreads();
    if (tid < 128) {
        float iv = 1.0f / (red[tid * 2] + red[tid * 2 + 1]);
        invg[(size_t)bh * Sc + row0 + tid] = iv;
        red2[tid] = iv;
    }
    __syncthreads();

    float* uRed = smf;   // reuse K0 region, stride 68
    if (wn == 1) {
#pragma unroll
        for (int nt = 0; nt < 8; nt++) {
            int rr = wm * 16 + g, cc = nt * 8 + c * 2;
            uRed[rr * 68 + cc]           = accU[nt][0];
            uRed[rr * 68 + cc + 1]       = accU[nt][1];
            uRed[(rr + 8) * 68 + cc]     = accU[nt][2];
            uRed[(rr + 8) * 68 + cc + 1] = accU[nt][3];
        }
    }
    __syncthreads();
    if (wn == 0) {
        float* cp = ctx + (size_t)(b * Sc + row0) * Dc + h * HDc;
        int rr = wm * 16 + g;
        float iv0 = red2[rr], iv1 = red2[rr + 8];
#pragma unroll
        for (int nt = 0; nt < 8; nt++) {
            int cc = nt * 8 + c * 2;
            float u0 = (accU[nt][0] + uRed[rr * 68 + cc]) * iv0;
            float u1 = (accU[nt][1] + uRed[rr * 68 + cc + 1]) * iv0;
            float u2 = (accU[nt][2] + uRed[(rr + 8) * 68 + cc]) * iv1;
            float u3 = (accU[nt][3] + uRed[(rr + 8) * 68 + cc + 1]) * iv1;
            cp[(size_t)rr * Dc + cc]           = tf32_round(u0);
            cp[(size_t)rr * Dc + cc + 1]       = tf32_round(u1);
            cp[(size_t)(rr + 8) * Dc + cc]     = tf32_round(u2);
            cp[(size_t)(rr + 8) * Dc + cc + 1] = tf32_round(u3);
        }
    }
}

// ============================================================================
// normalize attn in place: attn[row, :] *= inv[row]   (measured 6.55 TB/s)
// ============================================================================
__global__ void norm_k(float4* __restrict__ attn4, const float* __restrict__ inv) {
    const size_t total = (size_t)BHc * Sc * Sc / 4;
    size_t i = (size_t)blockIdx.x * blockDim.x + threadIdx.x;
    const size_t stride = (size_t)gridDim.x * blockDim.x;
    for (; i < total; i += stride) {
        float s = __ldg(&inv[i >> 9]);     // 512 float4 per row
        float4 v = attn4[i];
        v.x *= s; v.y *= s; v.z *= s; v.w *= s;
        attn4[i] = v;
    }
}

// ---------------------------------------------------------------------------
extern "C" void kernel_launch(void* const* d_in, const int* in_sizes, int n_in,
                              void* d_out, int out_size) {
    const float* query = (const float*)d_in[0];
    const float* key   = (const float*)d_in[1];
    const float* value = (const float*)d_in[2];
    const float* Wq = (const float*)d_in[3];
    const float* bq = (const float*)d_in[4];
    const float* Wk = (const float*)d_in[5];
    const float* bk = (const float*)d_in[6];
    const float* Wv = (const float*)d_in[7];
    const float* bv = (const float*)d_in[8];
    const float* Wo = (const float*)d_in[9];
    const float* bo = (const float*)d_in[10];

    float* out = (float*)d_out;
    const size_t OUT_E  = (size_t)Bc * Sc * Dc;
    const size_t ATTN_E = (size_t)BHc * Sc * Sc;

    float* attn;
    if ((size_t)out_size >= OUT_E + ATTN_E) {
        attn = out + OUT_E;
    } else {
        void* p = nullptr; cudaGetSymbolAddress(&p, g_attn_fb); attn = (float*)p;
    }
    float* Qp;   { void* p; cudaGetSymbolAddress(&p, g_Q);      Qp = (float*)p; }
    float* Kp;   { void* p; cudaGetSymbolAddress(&p, g_K);      Kp = (float*)p; }
    float* Vp;   { void* p; cudaGetSymbolAddress(&p, g_V);      Vp = (float*)p; }
    float* Cx;   { void* p; cudaGetSymbolAddress(&p, g_ctx);    Cx = (float*)p; }
    float* isum; { void* p; cudaGetSymbolAddress(&p, g_invsum); isum = (float*)p; }
    float* qin;  { void* p; cudaGetSymbolAddress(&p, g_qin);    qin = (float*)p; }
    float* kin;  { void* p; cudaGetSymbolAddress(&p, g_kin);    kin = (float*)p; }
    float* vin;  { void* p; cudaGetSymbolAddress(&p, g_vin);    vin = (float*)p; }
    float* wq;   { void* p; cudaGetSymbolAddress(&p, g_wq);     wq = (float*)p; }
    float* wk;   { void* p; cudaGetSymbolAddress(&p, g_wk);     wk = (float*)p; }
    float* wv;   { void* p; cudaGetSymbolAddress(&p, g_wv);     wv = (float*)p; }
    float* wo;   { void* p; cudaGetSymbolAddress(&p, g_wo);     wo = (float*)p; }

    cudaFuncSetAttribute(fused_attn, cudaFuncAttributeMaxDynamicSharedMemorySize,
                         FTOT * 4);
    cudaFuncSetAttribute(qkv_gemm, cudaFuncAttributeMaxDynamicSharedMemorySize,
                         GSMEM_BYTES);
    cudaFuncSetAttribute(gemm_bias_tc, cudaFuncAttributeMaxDynamicSharedMemorySize,
                         GSMEM_BYTES);

    const int M = Bc * Sc;                      // 4096
    dim3 thr(256);

    prep_round<<<dim3(256, 1, 7), thr>>>(
        (const float4*)query, (const float4*)key, (const float4*)value,
        (const float4*)Wq, (const float4*)Wk, (const float4*)Wv, (const float4*)Wo,
        (float4*)qin, (float4*)kin, (float4*)vin,
        (float4*)wq, (float4*)wk, (float4*)wv, (float4*)wo);

    qkv_gemm<<<dim3(Dc / 128, M / 128, 3), thr, GSMEM_BYTES>>>(
        qin, kin, vin, wq, bq, wk, bk, wv, bv, Qp, Kp, Vp);

    dim3 gfa(Sc / 128, BHc);                    // (16, 32)
    fused_attn<<<gfa, dim3(512), FTOT * 4>>>(Qp, Kp, Vp, attn, isum, Cx);

    norm_k<<<4736, 256>>>((float4*)attn, isum);

    gemm_bias_tc<<<dim3(Dc / 128, M / 128), thr, GSMEM_BYTES>>>(
        Cx, wo, bo, out, M, Dc, Dc);
}

// round 12
// speedup vs baseline: 1.0087x; 1.0087x over previous
#include <cuda_runtime.h>
#include <cstdint>

#define Bc 2
#define Sc 2048
#define Dc 1024
#define Hc 16
#define HDc 64
#define BHc (Bc*Hc)
#define SCALEc 0.125f              // 64^-0.5
#define KLOG2 0.1803368801111243f // SCALEc * log2(e)

// ---- scratch (allocation-free rule: __device__ globals) --------------------
__device__ float g_Q[(size_t)Bc * Sc * Dc];
__device__ float g_K[(size_t)Bc * Sc * Dc];
__device__ float g_V[(size_t)Bc * Sc * Dc];
__device__ float g_ctx[(size_t)Bc * Sc * Dc];
__device__ float g_invsum[(size_t)BHc * Sc];
// pre-rounded (tf32) copies of inputs + weights
__device__ float g_qin[(size_t)Bc * Sc * Dc];
__device__ float g_kin[(size_t)Bc * Sc * Dc];
__device__ float g_vin[(size_t)Bc * Sc * Dc];
__device__ float g_wq[(size_t)Dc * Dc];
__device__ float g_wk[(size_t)Dc * Dc];
__device__ float g_wv[(size_t)Dc * Dc];
__device__ float g_wo[(size_t)Dc * Dc];
__device__ float g_attn_fb[(size_t)BHc * Sc * Sc];   // fallback if out only holds `output`

// ---- helpers ----------------------------------------------------------------
__device__ __forceinline__ float tf32_round(float x) {
    return __uint_as_float((__float_as_uint(x) + 0x1000u) & 0xFFFFE000u);
}
__device__ __forceinline__ uint32_t f2tf(float x) {
    uint32_t r; asm("cvt.rna.tf32.f32 %0, %1;" : "=r"(r) : "f"(x)); return r;
}
__device__ __forceinline__ float ex2(float x) {
    float r; asm("ex2.approx.f32 %0, %1;" : "=f"(r) : "f"(x)); return r;
}
__device__ __forceinline__ void mma8(float* d, const uint32_t* a, const uint32_t* b) {
    asm volatile(
        "mma.sync.aligned.m16n8k8.row.col.f32.tf32.tf32.f32 "
        "{%0,%1,%2,%3}, {%4,%5,%6,%7}, {%8,%9}, {%0,%1,%2,%3};\n"
        : "+f"(d[0]), "+f"(d[1]), "+f"(d[2]), "+f"(d[3])
        : "r"(a[0]), "r"(a[1]), "r"(a[2]), "r"(a[3]), "r"(b[0]), "r"(b[1]));
}
__device__ __forceinline__ uint32_t smem_u32(const void* p) {
    uint32_t r;
    asm("{ .reg .u64 t; cvta.to.shared.u64 t, %1; cvt.u32.u64 %0, t; }"
        : "=r"(r) : "l"(p));
    return r;
}
__device__ __forceinline__ void cpa16(uint32_t saddr, const void* g) {
    asm volatile("cp.async.cg.shared.global [%0], [%1], 16;" :: "r"(saddr), "l"(g));
}
__device__ __forceinline__ void cpa_commit() { asm volatile("cp.async.commit_group;"); }
__device__ __forceinline__ void cpa_wait0()  { asm volatile("cp.async.wait_group 0;"); }
__device__ __forceinline__ void cpa_wait1()  { asm volatile("cp.async.wait_group 1;"); }

// ============================================================================
// prep: round inputs + weights to tf32 (producer-side rounding).
// ============================================================================
__global__ __launch_bounds__(256)
void prep_round(const float4* __restrict__ q, const float4* __restrict__ k,
                const float4* __restrict__ v,
                const float4* __restrict__ wq, const float4* __restrict__ wk,
                const float4* __restrict__ wv, const float4* __restrict__ wo,
                float4* __restrict__ oq, float4* __restrict__ ok,
                float4* __restrict__ ov,
                float4* __restrict__ owq, float4* __restrict__ owk,
                float4* __restrict__ owv, float4* __restrict__ owo) {
    const float4* src; float4* dst; size_t n4;
    const size_t NIN = (size_t)Bc * Sc * Dc / 4;
    const size_t NW  = (size_t)Dc * Dc / 4;
    switch (blockIdx.z) {
        case 0: src = q;  dst = oq;  n4 = NIN; break;
        case 1: src = k;  dst = ok;  n4 = NIN; break;
        case 2: src = v;  dst = ov;  n4 = NIN; break;
        case 3: src = wq; dst = owq; n4 = NW;  break;
        case 4: src = wk; dst = owk; n4 = NW;  break;
        case 5: src = wv; dst = owv; n4 = NW;  break;
        default: src = wo; dst = owo; n4 = NW;  break;
    }
    size_t i = (size_t)blockIdx.x * 256 + threadIdx.x;
    const size_t stride = (size_t)gridDim.x * 256;
    for (; i < n4; i += stride) {
        float4 t = src[i];
        t.x = tf32_round(t.x); t.y = tf32_round(t.y);
        t.z = tf32_round(t.z); t.w = tf32_round(t.w);
        dst[i] = t;
    }
}

// ============================================================================
// GEMM + bias: cp.async double-buffered, BK=16, pure-truncation tf32
// fragments (operands pre-rounded, so truncation == rna). Round-10 measured.
// ============================================================================
struct GemmSmem {
    float As[2][128][20];
    float Bs[2][16][136];
};

template<bool RND_OUT>
__device__ __forceinline__
void gemm_body(const float* __restrict__ A, const float* __restrict__ W,
               const float* __restrict__ bias, float* __restrict__ C,
               int M, int N, int K, GemmSmem& sm) {
    const int tid = threadIdx.x;
    const int lane = tid & 31, warp = tid >> 5;
    const int wm = warp >> 2, wn = warp & 3;
    const int row0 = blockIdx.y * 128, col0 = blockIdx.x * 128;
    const int r_lo = lane >> 2, c_lo = lane & 3;

    const int rowA = tid >> 1, colA = (tid & 1) * 8;
    const int rowB = tid >> 4, colB = (tid & 15) * 8;

    const uint32_t sA[2] = { smem_u32(&sm.As[0][rowA][colA]),
                             smem_u32(&sm.As[1][rowA][colA]) };
    const uint32_t sB[2] = { smem_u32(&sm.Bs[0][rowB][colB]),
                             smem_u32(&sm.Bs[1][rowB][colB]) };
    const float* gA = A + (size_t)(row0 + rowA) * K + colA;
    const float* gB = W + (size_t)rowB * N + col0 + colB;

    float acc[4][4][4] = {};

    cpa16(sA[0], gA); cpa16(sA[0] + 16, gA + 4);
    cpa16(sB[0], gB); cpa16(sB[0] + 16, gB + 4);
    cpa_commit();

    const int nk = K >> 4;
    for (int kt = 0; kt < nk; kt++) {
        const int s = kt & 1;
        if (kt + 1 < nk) {
            const float* gA2 = gA + (kt + 1) * 16;
            const float* gB2 = gB + (size_t)(kt + 1) * 16 * N;
            cpa16(sA[s ^ 1], gA2); cpa16(sA[s ^ 1] + 16, gA2 + 4);
            cpa16(sB[s ^ 1], gB2); cpa16(sB[s ^ 1] + 16, gB2 + 4);
            cpa_commit();
            cpa_wait1();
        } else {
            cpa_wait0();
        }
        __syncthreads();

        const float (*As_)[20]  = sm.As[s];
        const float (*Bs_)[136] = sm.Bs[s];
#pragma unroll
        for (int ks = 0; ks < 16; ks += 8) {
            uint32_t af[4][4], bf[4][2];
#pragma unroll
            for (int mt = 0; mt < 4; mt++) {
                int rb = wm * 64 + mt * 16 + r_lo;
                af[mt][0] = __float_as_uint(As_[rb][ks + c_lo]);
                af[mt][1] = __float_as_uint(As_[rb + 8][ks + c_lo]);
                af[mt][2] = __float_as_uint(As_[rb][ks + 4 + c_lo]);
                af[mt][3] = __float_as_uint(As_[rb + 8][ks + 4 + c_lo]);
            }
#pragma unroll
            for (int nt = 0; nt < 4; nt++) {
                int cb = wn * 32 + nt * 8 + r_lo;
                bf[nt][0] = __float_as_uint(Bs_[ks + c_lo][cb]);
                bf[nt][1] = __float_as_uint(Bs_[ks + 4 + c_lo][cb]);
            }
#pragma unroll
            for (int mt = 0; mt < 4; mt++)
#pragma unroll
                for (int nt = 0; nt < 4; nt++)
                    mma8(acc[mt][nt], af[mt], bf[nt]);
        }
        __syncthreads();
    }

#pragma unroll
    for (int mt = 0; mt < 4; mt++) {
        int row = row0 + wm * 64 + mt * 16 + r_lo;
#pragma unroll
        for (int nt = 0; nt < 4; nt++) {
            int col = col0 + wn * 32 + nt * 8 + c_lo * 2;
            float b0 = bias[col], b1 = bias[col + 1];
            float v0 = acc[mt][nt][0] + b0, v1 = acc[mt][nt][1] + b1;
            float v2 = acc[mt][nt][2] + b0, v3 = acc[mt][nt][3] + b1;
            if (RND_OUT) {
                v0 = tf32_round(v0); v1 = tf32_round(v1);
                v2 = tf32_round(v2); v3 = tf32_round(v3);
            }
            C[(size_t)row * N + col]           = v0;
            C[(size_t)row * N + col + 1]       = v1;
            C[(size_t)(row + 8) * N + col]     = v2;
            C[(size_t)(row + 8) * N + col + 1] = v3;
        }
    }
}

__global__ __launch_bounds__(256)
void gemm_bias_tc(const float* __restrict__ A, const float* __restrict__ W,
                  const float* __restrict__ bias, float* __restrict__ C,
                  int M, int N, int K) {
    __shared__ GemmSmem sm;
    gemm_body<false>(A, W, bias, C, M, N, K, sm);
}

__global__ __launch_bounds__(256)
void qkv_gemm(const float* __restrict__ q, const float* __restrict__ k,
              const float* __restrict__ v,
              const float* __restrict__ Wq, const float* __restrict__ bq,
              const float* __restrict__ Wk, const float* __restrict__ bk,
              const float* __restrict__ Wv, const float* __restrict__ bv,
              float* __restrict__ Qo, float* __restrict__ Ko, float* __restrict__ Vo) {
    __shared__ GemmSmem sm;
    const float *A, *W, *bias; float* C;
    if (blockIdx.z == 0)      { A = q; W = Wq; bias = bq; C = Qo; }
    else if (blockIdx.z == 1) { A = k; W = Wk; bias = bk; C = Ko; }
    else                      { A = v; W = Wv; bias = bv; C = Vo; }
    gemm_body<true>(A, W, bias, C, Bc * Sc, Dc, Dc, sm);
}

// ============================================================================
// Fused attention — round-10 measured config: 512 threads (16 warps, 8m x 2n),
// 128 q-rows/block, 128-key K/V tiles double-buffered, stride 68.
// ============================================================================
#define FK0 0
#define FK1 8704
#define FV0 17408
#define FV1 26112
#define FRED 34816
#define FRED2 35072
#define FTOT 35200            // *4 = 140800 bytes

__global__ __launch_bounds__(512)
void fused_attn(const float* __restrict__ Qp, const float* __restrict__ Kp,
                const float* __restrict__ Vp, float* __restrict__ attn,
                float* __restrict__ invg, float* __restrict__ ctx) {
    extern __shared__ float smf[];
    const uint32_t sbase = smem_u32(smf);

    const int bh = blockIdx.y, b = bh >> 4, h = bh & 15;
    const int row0 = blockIdx.x * 128;
    const float* Qh = Qp + (size_t)b * Sc * Dc + h * HDc;
    const float* Kh = Kp + (size_t)b * Sc * Dc + h * HDc;
    const float* Vh = Vp + (size_t)b * Sc * Dc + h * HDc;
    float* outp = attn + (size_t)bh * Sc * Sc;

    const int tid = threadIdx.x, lane = tid & 31, warp = tid >> 5;
    const int wm = warp >> 1, wn = warp & 1;   // 8m x 2n
    const int g = lane >> 2, c = lane & 3;

    const int ldr0 = tid >> 4;                 // rows 0..31 (+32 per i)
    const int ldc4 = (tid & 15) * 4;

    {
#pragma unroll
        for (int i = 0; i < 4; i++) {
            int r = ldr0 + i * 32;
            cpa16(sbase + (uint32_t)(FK0 + r * 68 + ldc4) * 4, Kh + (size_t)r * Dc + ldc4);
            cpa16(sbase + (uint32_t)(FV0 + r * 68 + ldc4) * 4, Vh + (size_t)r * Dc + ldc4);
        }
        cpa_commit();
    }

    // Q fragments: raw bits (Qp pre-rounded to tf32 by qkv epilogue)
    uint32_t qf[8][4];
    {
        const int qr = row0 + wm * 16;
#pragma unroll
        for (int s8 = 0; s8 < 8; s8++) {
            qf[s8][0] = __float_as_uint(Qh[(size_t)(qr + g)     * Dc + s8 * 8 + c]);
            qf[s8][1] = __float_as_uint(Qh[(size_t)(qr + g + 8) * Dc + s8 * 8 + c]);
            qf[s8][2] = __float_as_uint(Qh[(size_t)(qr + g)     * Dc + s8 * 8 + c + 4]);
            qf[s8][3] = __float_as_uint(Qh[(size_t)(qr + g + 8) * Dc + s8 * 8 + c + 4]);
        }
    }

    cpa_wait0();
    __syncthreads();

    float accU[8][4] = {};
    float rs0 = 0.f, rs1 = 0.f;

    const int src1 = (lane & ~3) | (c >> 1);
    const int src2 = src1 + 2;
    const bool odd = (c & 1);

    for (int kt = 0; kt < 16; kt++) {
        const int s = kt & 1;
        if (kt + 1 < 16) {
            const float* gk = Kh + (size_t)((kt + 1) * 128) * Dc;
            const float* gv = Vh + (size_t)((kt + 1) * 128) * Dc;
            const int KD = s ? FK0 : FK1;
            const int VD = s ? FV0 : FV1;
#pragma unroll
            for (int i = 0; i < 4; i++) {
                int r = ldr0 + i * 32;
                cpa16(sbase + (uint32_t)(KD + r * 68 + ldc4) * 4, gk + (size_t)r * Dc + ldc4);
                cpa16(sbase + (uint32_t)(VD + r * 68 + ldc4) * 4, gv + (size_t)r * Dc + ldc4);
            }
            cpa_commit();
        }
        const float* sK = smf + (s ? FK1 : FK0);
        const float* sV = smf + (s ? FV1 : FV0);
        const int k0 = kt * 128;

#pragma unroll
        for (int half = 0; half < 2; half++) {
            const int colbase = wn * 64 + half * 32;

            float accS[4][4] = {};
#pragma unroll
            for (int s8 = 0; s8 < 8; s8++) {
                uint32_t bf[4][2];
#pragma unroll
                for (int nt = 0; nt < 4; nt++) {
                    int kc = colbase + nt * 8 + g;
                    bf[nt][0] = __float_as_uint(sK[kc * 68 + s8 * 8 + c]);
                    bf[nt][1] = __float_as_uint(sK[kc * 68 + s8 * 8 + c + 4]);
                }
#pragma unroll
                for (int nt = 0; nt < 4; nt++)
                    mma8(accS[nt], qf[s8], bf[nt]);
            }

            const int grow = row0 + wm * 16 + g;
#pragma unroll
            for (int nt = 0; nt < 4; nt++) {
                float e0 = ex2(accS[nt][0] * KLOG2);
                float e1 = ex2(accS[nt][1] * KLOG2);
                float e2 = ex2(accS[nt][2] * KLOG2);
                float e3 = ex2(accS[nt][3] * KLOG2);
                rs0 += e0 + e1; rs1 += e2 + e3;
                int gcol = k0 + colbase + nt * 8 + c * 2;
                *reinterpret_cast<float2*>(&outp[(size_t)grow * Sc + gcol])       = make_float2(e0, e1);
                *reinterpret_cast<float2*>(&outp[(size_t)(grow + 8) * Sc + gcol]) = make_float2(e2, e3);
                accS[nt][0] = e0; accS[nt][1] = e1; accS[nt][2] = e2; accS[nt][3] = e3;
            }

#pragma unroll
            for (int s4 = 0; s4 < 4; s4++) {
                float x0 = __shfl_sync(0xffffffffu, accS[s4][0], src1);
                float x1 = __shfl_sync(0xffffffffu, accS[s4][1], src1);
                float y0 = __shfl_sync(0xffffffffu, accS[s4][2], src1);
                float y1 = __shfl_sync(0xffffffffu, accS[s4][3], src1);
                float z0 = __shfl_sync(0xffffffffu, accS[s4][0], src2);
                float z1 = __shfl_sync(0xffffffffu, accS[s4][1], src2);
                float w0 = __shfl_sync(0xffffffffu, accS[s4][2], src2);
                float w1 = __shfl_sync(0xffffffffu, accS[s4][3], src2);
                uint32_t af[4];
                af[0] = f2tf(odd ? x1 : x0);
                af[1] = f2tf(odd ? y1 : y0);
                af[2] = f2tf(odd ? z1 : z0);
                af[3] = f2tf(odd ? w1 : w0);
                const int vr = colbase + s4 * 8 + c;
#pragma unroll
                for (int nt = 0; nt < 8; nt++) {
                    uint32_t bf[2];
                    bf[0] = __float_as_uint(sV[vr * 68 + nt * 8 + g]);
                    bf[1] = __float_as_uint(sV[(vr + 4) * 68 + nt * 8 + g]);
                    mma8(accU[nt], af, bf);
                }
            }
        }

        if (kt + 1 < 16) cpa_wait0();
        __syncthreads();
    }

    float* red  = smf + FRED;
    float* red2 = smf + FRED2;
    {
        float v0 = rs0, v1 = rs1;
        v0 += __shfl_xor_sync(0xffffffffu, v0, 1);
        v0 += __shfl_xor_sync(0xffffffffu, v0, 2);
        v1 += __shfl_xor_sync(0xffffffffu, v1, 1);
        v1 += __shfl_xor_sync(0xffffffffu, v1, 2);
        if (c == 0) {
            red[(wm * 16 + g) * 2 + wn]     = v0;
            red[(wm * 16 + g + 8) * 2 + wn] = v1;
        }
    }
    __syncthreads();
    if (tid < 128) {
        float iv = 1.0f / (red[tid * 2] + red[tid * 2 + 1]);
        invg[(size_t)bh * Sc + row0 + tid] = iv;
        red2[tid] = iv;
    }
    __syncthreads();

    float* uRed = smf;
    if (wn == 1) {
#pragma unroll
        for (int nt = 0; nt < 8; nt++) {
            int rr = wm * 16 + g, cc = nt * 8 + c * 2;
            uRed[rr * 68 + cc]           = accU[nt][0];
            uRed[rr * 68 + cc + 1]       = accU[nt][1];
            uRed[(rr + 8) * 68 + cc]     = accU[nt][2];
            uRed[(rr + 8) * 68 + cc + 1] = accU[nt][3];
        }
    }
    __syncthreads();
    if (wn == 0) {
        float* cp = ctx + (size_t)(b * Sc + row0) * Dc + h * HDc;
        int rr = wm * 16 + g;
        float iv0 = red2[rr], iv1 = red2[rr + 8];
#pragma unroll
        for (int nt = 0; nt < 8; nt++) {
            int cc = nt * 8 + c * 2;
            float u0 = (accU[nt][0] + uRed[rr * 68 + cc]) * iv0;
            float u1 = (accU[nt][1] + uRed[rr * 68 + cc + 1]) * iv0;
            float u2 = (accU[nt][2] + uRed[(rr + 8) * 68 + cc]) * iv1;
            float u3 = (accU[nt][3] + uRed[(rr + 8) * 68 + cc + 1]) * iv1;
            cp[(size_t)rr * Dc + cc]           = tf32_round(u0);
            cp[(size_t)rr * Dc + cc + 1]       = tf32_round(u1);
            cp[(size_t)(rr + 8) * Dc + cc]     = tf32_round(u2);
            cp[(size_t)(rr + 8) * Dc + cc + 1] = tf32_round(u3);
        }
    }
}

// ============================================================================
// normalize attn in place: attn[row, :] *= inv[row]   (measured 6.55 TB/s)
// ============================================================================
__global__ void norm_k(float4* __restrict__ attn4, const float* __restrict__ inv) {
    const size_t total = (size_t)BHc * Sc * Sc / 4;
    size_t i = (size_t)blockIdx.x * blockDim.x + threadIdx.x;
    const size_t stride = (size_t)gridDim.x * blockDim.x;
    for (; i < total; i += stride) {
        float s = __ldg(&inv[i >> 9]);     // 512 float4 per row
        float4 v = attn4[i];
        v.x *= s; v.y *= s; v.z *= s; v.w *= s;
        attn4[i] = v;
    }
}

// ---------------------------------------------------------------------------
// Side stream + events for the norm/out-proj overlap. Host-side objects
// created once (first call is the eager correctness run — capture-safe).
// The captured GPU work is identical on every call.
// ---------------------------------------------------------------------------
static cudaStream_t get_s2() {
    static cudaStream_t s = []{
        cudaStream_t t; cudaStreamCreateWithFlags(&t, cudaStreamNonBlocking); return t;
    }();
    return s;
}
static cudaEvent_t get_ev(int which) {
    static cudaEvent_t e0 = []{
        cudaEvent_t e; cudaEventCreateWithFlags(&e, cudaEventDisableTiming); return e;
    }();
    static cudaEvent_t e1 = []{
        cudaEvent_t e; cudaEventCreateWithFlags(&e, cudaEventDisableTiming); return e;
    }();
    return which == 0 ? e0 : e1;
}

extern "C" void kernel_launch(void* const* d_in, const int* in_sizes, int n_in,
                              void* d_out, int out_size) {
    const float* query = (const float*)d_in[0];
    const float* key   = (const float*)d_in[1];
    const float* value = (const float*)d_in[2];
    const float* Wq = (const float*)d_in[3];
    const float* bq = (const float*)d_in[4];
    const float* Wk = (const float*)d_in[5];
    const float* bk = (const float*)d_in[6];
    const float* Wv = (const float*)d_in[7];
    const float* bv = (const float*)d_in[8];
    const float* Wo = (const float*)d_in[9];
    const float* bo = (const float*)d_in[10];

    float* out = (float*)d_out;
    const size_t OUT_E  = (size_t)Bc * Sc * Dc;
    const size_t ATTN_E = (size_t)BHc * Sc * Sc;

    float* attn;
    if ((size_t)out_size >= OUT_E + ATTN_E) {
        attn = out + OUT_E;
    } else {
        void* p = nullptr; cudaGetSymbolAddress(&p, g_attn_fb); attn = (float*)p;
    }
    float* Qp;   { void* p; cudaGetSymbolAddress(&p, g_Q);      Qp = (float*)p; }
    float* Kp;   { void* p; cudaGetSymbolAddress(&p, g_K);      Kp = (float*)p; }
    float* Vp;   { void* p; cudaGetSymbolAddress(&p, g_V);      Vp = (float*)p; }
    float* Cx;   { void* p; cudaGetSymbolAddress(&p, g_ctx);    Cx = (float*)p; }
    float* isum; { void* p; cudaGetSymbolAddress(&p, g_invsum); isum = (float*)p; }
    float* qin;  { void* p; cudaGetSymbolAddress(&p, g_qin);    qin = (float*)p; }
    float* kin;  { void* p; cudaGetSymbolAddress(&p, g_kin);    kin = (float*)p; }
    float* vin;  { void* p; cudaGetSymbolAddress(&p, g_vin);    vin = (float*)p; }
    float* wq;   { void* p; cudaGetSymbolAddress(&p, g_wq);     wq = (float*)p; }
    float* wk;   { void* p; cudaGetSymbolAddress(&p, g_wk);     wk = (float*)p; }
    float* wv;   { void* p; cudaGetSymbolAddress(&p, g_wv);     wv = (float*)p; }
    float* wo;   { void* p; cudaGetSymbolAddress(&p, g_wo);     wo = (float*)p; }

    cudaFuncSetAttribute(fused_attn, cudaFuncAttributeMaxDynamicSharedMemorySize,
                         FTOT * 4);

    cudaStream_t s2 = get_s2();
    cudaEvent_t evFork = get_ev(0), evJoin = get_ev(1);

    const int M = Bc * Sc;                      // 4096
    dim3 thr(256);

    prep_round<<<dim3(256, 1, 7), thr>>>(
        (const float4*)query, (const float4*)key, (const float4*)value,
        (const float4*)Wq, (const float4*)Wk, (const float4*)Wv, (const float4*)Wo,
        (float4*)qin, (float4*)kin, (float4*)vin,
        (float4*)wq, (float4*)wk, (float4*)wv, (float4*)wo);

    qkv_gemm<<<dim3(Dc / 128, M / 128, 3), thr>>>(qin, kin, vin,
                                                  wq, bq, wk, bk, wv, bv,
                                                  Qp, Kp, Vp);

    dim3 gfa(Sc / 128, BHc);                    // (16, 32)
    fused_attn<<<gfa, dim3(512), FTOT * 4>>>(Qp, Kp, Vp, attn, isum, Cx);

    // fork: norm_k (DRAM-bound) on s2 concurrently with out-proj (tensor-bound)
    cudaEventRecord(evFork, 0);
    cudaStreamWaitEvent(s2, evFork, 0);

    norm_k<<<4736, 256, 0, s2>>>((float4*)attn, isum);

    gemm_bias_tc<<<dim3(Dc / 128, M / 128), thr>>>(Cx, wo, bo, out, M, Dc, Dc);

    // join: default stream waits for norm before returning
    cudaEventRecord(evJoin, s2);
    cudaStreamWaitEvent(0, evJoin, 0);
}

// round 13
// speedup vs baseline: 1.0433x; 1.0344x over previous
#include <cuda_runtime.h>
#include <cstdint>

#define Bc 2
#define Sc 2048
#define Dc 1024
#define Hc 16
#define HDc 64
#define BHc (Bc*Hc)
#define SCALEc 0.125f              // 64^-0.5
#define KLOG2 0.1803368801111243f // SCALEc * log2(e)

// ---- scratch (allocation-free rule: __device__ globals) --------------------
__device__ float g_Q[(size_t)Bc * Sc * Dc];
__device__ float g_K[(size_t)Bc * Sc * Dc];
__device__ float g_V[(size_t)Bc * Sc * Dc];
__device__ float g_ctx[(size_t)Bc * Sc * Dc];
__device__ float g_invsum[(size_t)BHc * Sc];
// pre-rounded (tf32) copies of inputs + weights
__device__ float g_qin[(size_t)Bc * Sc * Dc];
__device__ float g_kin[(size_t)Bc * Sc * Dc];
__device__ float g_vin[(size_t)Bc * Sc * Dc];
__device__ float g_wq[(size_t)Dc * Dc];
__device__ float g_wk[(size_t)Dc * Dc];
__device__ float g_wv[(size_t)Dc * Dc];
__device__ float g_wo[(size_t)Dc * Dc];
__device__ float g_attn_fb[(size_t)BHc * Sc * Sc];   // fallback if out only holds `output`

// ---- helpers ----------------------------------------------------------------
__device__ __forceinline__ float tf32_round(float x) {
    return __uint_as_float((__float_as_uint(x) + 0x1000u) & 0xFFFFE000u);
}
__device__ __forceinline__ uint32_t f2tf(float x) {
    uint32_t r; asm("cvt.rna.tf32.f32 %0, %1;" : "=r"(r) : "f"(x)); return r;
}
__device__ __forceinline__ float ex2(float x) {
    float r; asm("ex2.approx.f32 %0, %1;" : "=f"(r) : "f"(x)); return r;
}
__device__ __forceinline__ void mma8(float* d, const uint32_t* a, const uint32_t* b) {
    asm volatile(
        "mma.sync.aligned.m16n8k8.row.col.f32.tf32.tf32.f32 "
        "{%0,%1,%2,%3}, {%4,%5,%6,%7}, {%8,%9}, {%0,%1,%2,%3};\n"
        : "+f"(d[0]), "+f"(d[1]), "+f"(d[2]), "+f"(d[3])
        : "r"(a[0]), "r"(a[1]), "r"(a[2]), "r"(a[3]), "r"(b[0]), "r"(b[1]));
}
__device__ __forceinline__ uint32_t smem_u32(const void* p) {
    uint32_t r;
    asm("{ .reg .u64 t; cvta.to.shared.u64 t, %1; cvt.u32.u64 %0, t; }"
        : "=r"(r) : "l"(p));
    return r;
}
__device__ __forceinline__ void cpa16(uint32_t saddr, const void* g) {
    asm volatile("cp.async.cg.shared.global [%0], [%1], 16;" :: "r"(saddr), "l"(g));
}
__device__ __forceinline__ void cpa_commit() { asm volatile("cp.async.commit_group;"); }
__device__ __forceinline__ void cpa_wait0()  { asm volatile("cp.async.wait_group 0;"); }
__device__ __forceinline__ void cpa_wait1()  { asm volatile("cp.async.wait_group 1;"); }

// ============================================================================
// prep: round inputs + weights to tf32 (producer-side rounding).
// ============================================================================
__global__ __launch_bounds__(256)
void prep_round(const float4* __restrict__ q, const float4* __restrict__ k,
                const float4* __restrict__ v,
                const float4* __restrict__ wq, const float4* __restrict__ wk,
                const float4* __restrict__ wv, const float4* __restrict__ wo,
                float4* __restrict__ oq, float4* __restrict__ ok,
                float4* __restrict__ ov,
                float4* __restrict__ owq, float4* __restrict__ owk,
                float4* __restrict__ owv, float4* __restrict__ owo) {
    const float4* src; float4* dst; size_t n4;
    const size_t NIN = (size_t)Bc * Sc * Dc / 4;
    const size_t NW  = (size_t)Dc * Dc / 4;
    switch (blockIdx.z) {
        case 0: src = q;  dst = oq;  n4 = NIN; break;
        case 1: src = k;  dst = ok;  n4 = NIN; break;
        case 2: src = v;  dst = ov;  n4 = NIN; break;
        case 3: src = wq; dst = owq; n4 = NW;  break;
        case 4: src = wk; dst = owk; n4 = NW;  break;
        case 5: src = wv; dst = owv; n4 = NW;  break;
        default: src = wo; dst = owo; n4 = NW;  break;
    }
    size_t i = (size_t)blockIdx.x * 256 + threadIdx.x;
    const size_t stride = (size_t)gridDim.x * 256;
    for (; i < n4; i += stride) {
        float4 t = src[i];
        t.x = tf32_round(t.x); t.y = tf32_round(t.y);
        t.z = tf32_round(t.z); t.w = tf32_round(t.w);
        dst[i] = t;
    }
}

// ============================================================================
// GEMM + bias: cp.async double-buffered, BK=16, pure-truncation tf32
// fragments (operands pre-rounded, so truncation == rna).
// ============================================================================
struct GemmSmem {
    float As[2][128][20];
    float Bs[2][16][136];
};

template<bool RND_OUT>
__device__ __forceinline__
void gemm_body(const float* __restrict__ A, const float* __restrict__ W,
               const float* __restrict__ bias, float* __restrict__ C,
               int M, int N, int K, GemmSmem& sm) {
    const int tid = threadIdx.x;
    const int lane = tid & 31, warp = tid >> 5;
    const int wm = warp >> 2, wn = warp & 3;
    const int row0 = blockIdx.y * 128, col0 = blockIdx.x * 128;
    const int r_lo = lane >> 2, c_lo = lane & 3;

    const int rowA = tid >> 1, colA = (tid & 1) * 8;
    const int rowB = tid >> 4, colB = (tid & 15) * 8;

    const uint32_t sA[2] = { smem_u32(&sm.As[0][rowA][colA]),
                             smem_u32(&sm.As[1][rowA][colA]) };
    const uint32_t sB[2] = { smem_u32(&sm.Bs[0][rowB][colB]),
                             smem_u32(&sm.Bs[1][rowB][colB]) };
    const float* gA = A + (size_t)(row0 + rowA) * K + colA;
    const float* gB = W + (size_t)rowB * N + col0 + colB;

    float acc[4][4][4] = {};

    cpa16(sA[0], gA); cpa16(sA[0] + 16, gA + 4);
    cpa16(sB[0], gB); cpa16(sB[0] + 16, gB + 4);
    cpa_commit();

    const int nk = K >> 4;
    for (int kt = 0; kt < nk; kt++) {
        const int s = kt & 1;
        if (kt + 1 < nk) {
            const float* gA2 = gA + (kt + 1) * 16;
            const float* gB2 = gB + (size_t)(kt + 1) * 16 * N;
            cpa16(sA[s ^ 1], gA2); cpa16(sA[s ^ 1] + 16, gA2 + 4);
            cpa16(sB[s ^ 1], gB2); cpa16(sB[s ^ 1] + 16, gB2 + 4);
            cpa_commit();
            cpa_wait1();
        } else {
            cpa_wait0();
        }
        __syncthreads();

        const float (*As_)[20]  = sm.As[s];
        const float (*Bs_)[136] = sm.Bs[s];
#pragma unroll
        for (int ks = 0; ks < 16; ks += 8) {
            uint32_t af[4][4], bf[4][2];
#pragma unroll
            for (int mt = 0; mt < 4; mt++) {
                int rb = wm * 64 + mt * 16 + r_lo;
                af[mt][0] = __float_as_uint(As_[rb][ks + c_lo]);
                af[mt][1] = __float_as_uint(As_[rb + 8][ks + c_lo]);
                af[mt][2] = __float_as_uint(As_[rb][ks + 4 + c_lo]);
                af[mt][3] = __float_as_uint(As_[rb + 8][ks + 4 + c_lo]);
            }
#pragma unroll
            for (int nt = 0; nt < 4; nt++) {
                int cb = wn * 32 + nt * 8 + r_lo;
                bf[nt][0] = __float_as_uint(Bs_[ks + c_lo][cb]);
                bf[nt][1] = __float_as_uint(Bs_[ks + 4 + c_lo][cb]);
            }
#pragma unroll
            for (int mt = 0; mt < 4; mt++)
#pragma unroll
                for (int nt = 0; nt < 4; nt++)
                    mma8(acc[mt][nt], af[mt], bf[nt]);
        }
        __syncthreads();
    }

#pragma unroll
    for (int mt = 0; mt < 4; mt++) {
        int row = row0 + wm * 64 + mt * 16 + r_lo;
#pragma unroll
        for (int nt = 0; nt < 4; nt++) {
            int col = col0 + wn * 32 + nt * 8 + c_lo * 2;
            float b0 = bias[col], b1 = bias[col + 1];
            float v0 = acc[mt][nt][0] + b0, v1 = acc[mt][nt][1] + b1;
            float v2 = acc[mt][nt][2] + b0, v3 = acc[mt][nt][3] + b1;
            if (RND_OUT) {
                v0 = tf32_round(v0); v1 = tf32_round(v1);
                v2 = tf32_round(v2); v3 = tf32_round(v3);
            }
            C[(size_t)row * N + col]           = v0;
            C[(size_t)row * N + col + 1]       = v1;
            C[(size_t)(row + 8) * N + col]     = v2;
            C[(size_t)(row + 8) * N + col + 1] = v3;
        }
    }
}

__global__ __launch_bounds__(256)
void gemm_bias_tc(const float* __restrict__ A, const float* __restrict__ W,
                  const float* __restrict__ bias, float* __restrict__ C,
                  int M, int N, int K) {
    __shared__ GemmSmem sm;
    gemm_body<false>(A, W, bias, C, M, N, K, sm);
}

__global__ __launch_bounds__(256)
void qkv_gemm(const float* __restrict__ q, const float* __restrict__ k,
              const float* __restrict__ v,
              const float* __restrict__ Wq, const float* __restrict__ bq,
              const float* __restrict__ Wk, const float* __restrict__ bk,
              const float* __restrict__ Wv, const float* __restrict__ bv,
              float* __restrict__ Qo, float* __restrict__ Ko, float* __restrict__ Vo) {
    __shared__ GemmSmem sm;
    const float *A, *W, *bias; float* C;
    if (blockIdx.z == 0)      { A = q; W = Wq; bias = bq; C = Qo; }
    else if (blockIdx.z == 1) { A = k; W = Wk; bias = bk; C = Ko; }
    else                      { A = v; W = Wv; bias = bv; C = Vo; }
    gemm_body<true>(A, W, bias, C, Bc * Sc, Dc, Dc, sm);
}

// ============================================================================
// Fused attention — round-10 measured config: 512 threads (16 warps, 8m x 2n),
// 128 q-rows/block, 128-key K/V tiles double-buffered, stride 68.
// ============================================================================
#define FK0 0
#define FK1 8704
#define FV0 17408
#define FV1 26112
#define FRED 34816
#define FRED2 35072
#define FTOT 35200            // *4 = 140800 bytes

__global__ __launch_bounds__(512)
void fused_attn(const float* __restrict__ Qp, const float* __restrict__ Kp,
                const float* __restrict__ Vp, float* __restrict__ attn,
                float* __restrict__ invg, float* __restrict__ ctx) {
    extern __shared__ float smf[];
    const uint32_t sbase = smem_u32(smf);

    const int bh = blockIdx.y, b = bh >> 4, h = bh & 15;
    const int row0 = blockIdx.x * 128;
    const float* Qh = Qp + (size_t)b * Sc * Dc + h * HDc;
    const float* Kh = Kp + (size_t)b * Sc * Dc + h * HDc;
    const float* Vh = Vp + (size_t)b * Sc * Dc + h * HDc;
    float* outp = attn + (size_t)bh * Sc * Sc;

    const int tid = threadIdx.x, lane = tid & 31, warp = tid >> 5;
    const int wm = warp >> 1, wn = warp & 1;   // 8m x 2n
    const int g = lane >> 2, c = lane & 3;

    const int ldr0 = tid >> 4;                 // rows 0..31 (+32 per i)
    const int ldc4 = (tid & 15) * 4;

    {
#pragma unroll
        for (int i = 0; i < 4; i++) {
            int r = ldr0 + i * 32;
            cpa16(sbase + (uint32_t)(FK0 + r * 68 + ldc4) * 4, Kh + (size_t)r * Dc + ldc4);
            cpa16(sbase + (uint32_t)(FV0 + r * 68 + ldc4) * 4, Vh + (size_t)r * Dc + ldc4);
        }
        cpa_commit();
    }

    // Q fragments: raw bits (Qp pre-rounded to tf32 by qkv epilogue)
    uint32_t qf[8][4];
    {
        const int qr = row0 + wm * 16;
#pragma unroll
        for (int s8 = 0; s8 < 8; s8++) {
            qf[s8][0] = __float_as_uint(Qh[(size_t)(qr + g)     * Dc + s8 * 8 + c]);
            qf[s8][1] = __float_as_uint(Qh[(size_t)(qr + g + 8) * Dc + s8 * 8 + c]);
            qf[s8][2] = __float_as_uint(Qh[(size_t)(qr + g)     * Dc + s8 * 8 + c + 4]);
            qf[s8][3] = __float_as_uint(Qh[(size_t)(qr + g + 8) * Dc + s8 * 8 + c + 4]);
        }
    }

    cpa_wait0();
    __syncthreads();

    float accU[8][4] = {};
    float rs0 = 0.f, rs1 = 0.f;

    const int src1 = (lane & ~3) | (c >> 1);
    const int src2 = src1 + 2;
    const bool odd = (c & 1);

    for (int kt = 0; kt < 16; kt++) {
        const int s = kt & 1;
        if (kt + 1 < 16) {
            const float* gk = Kh + (size_t)((kt + 1) * 128) * Dc;
            const float* gv = Vh + (size_t)((kt + 1) * 128) * Dc;
            const int KD = s ? FK0 : FK1;
            const int VD = s ? FV0 : FV1;
#pragma unroll
            for (int i = 0; i < 4; i++) {
                int r = ldr0 + i * 32;
                cpa16(sbase + (uint32_t)(KD + r * 68 + ldc4) * 4, gk + (size_t)r * Dc + ldc4);
                cpa16(sbase + (uint32_t)(VD + r * 68 + ldc4) * 4, gv + (size_t)r * Dc + ldc4);
            }
            cpa_commit();
        }
        const float* sK = smf + (s ? FK1 : FK0);
        const float* sV = smf + (s ? FV1 : FV0);
        const int k0 = kt * 128;

#pragma unroll
        for (int half = 0; half < 2; half++) {
            const int colbase = wn * 64 + half * 32;

            float accS[4][4] = {};
#pragma unroll
            for (int s8 = 0; s8 < 8; s8++) {
                uint32_t bf[4][2];
#pragma unroll
                for (int nt = 0; nt < 4; nt++) {
                    int kc = colbase + nt * 8 + g;
                    bf[nt][0] = __float_as_uint(sK[kc * 68 + s8 * 8 + c]);
                    bf[nt][1] = __float_as_uint(sK[kc * 68 + s8 * 8 + c + 4]);
                }
#pragma unroll
                for (int nt = 0; nt < 4; nt++)
                    mma8(accS[nt], qf[s8], bf[nt]);
            }

            const int grow = row0 + wm * 16 + g;
#pragma unroll
            for (int nt = 0; nt < 4; nt++) {
                float e0 = ex2(accS[nt][0] * KLOG2);
                float e1 = ex2(accS[nt][1] * KLOG2);
                float e2 = ex2(accS[nt][2] * KLOG2);
                float e3 = ex2(accS[nt][3] * KLOG2);
                rs0 += e0 + e1; rs1 += e2 + e3;
                int gcol = k0 + colbase + nt * 8 + c * 2;
                *reinterpret_cast<float2*>(&outp[(size_t)grow * Sc + gcol])       = make_float2(e0, e1);
                *reinterpret_cast<float2*>(&outp[(size_t)(grow + 8) * Sc + gcol]) = make_float2(e2, e3);
                accS[nt][0] = e0; accS[nt][1] = e1; accS[nt][2] = e2; accS[nt][3] = e3;
            }

#pragma unroll
            for (int s4 = 0; s4 < 4; s4++) {
                float x0 = __shfl_sync(0xffffffffu, accS[s4][0], src1);
                float x1 = __shfl_sync(0xffffffffu, accS[s4][1], src1);
                float y0 = __shfl_sync(0xffffffffu, accS[s4][2], src1);
                float y1 = __shfl_sync(0xffffffffu, accS[s4][3], src1);
                float z0 = __shfl_sync(0xffffffffu, accS[s4][0], src2);
                float z1 = __shfl_sync(0xffffffffu, accS[s4][1], src2);
                float w0 = __shfl_sync(0xffffffffu, accS[s4][2], src2);
                float w1 = __shfl_sync(0xffffffffu, accS[s4][3], src2);
                uint32_t af[4];
                af[0] = f2tf(odd ? x1 : x0);
                af[1] = f2tf(odd ? y1 : y0);
                af[2] = f2tf(odd ? z1 : z0);
                af[3] = f2tf(odd ? w1 : w0);
                const int vr = colbase + s4 * 8 + c;
#pragma unroll
                for (int nt = 0; nt < 8; nt++) {
                    uint32_t bf[2];
                    bf[0] = __float_as_uint(sV[vr * 68 + nt * 8 + g]);
                    bf[1] = __float_as_uint(sV[(vr + 4) * 68 + nt * 8 + g]);
                    mma8(accU[nt], af, bf);
                }
            }
        }

        if (kt + 1 < 16) cpa_wait0();
        __syncthreads();
    }

    float* red  = smf + FRED;
    float* red2 = smf + FRED2;
    {
        float v0 = rs0, v1 = rs1;
        v0 += __shfl_xor_sync(0xffffffffu, v0, 1);
        v0 += __shfl_xor_sync(0xffffffffu, v0, 2);
        v1 += __shfl_xor_sync(0xffffffffu, v1, 1);
        v1 += __shfl_xor_sync(0xffffffffu, v1, 2);
        if (c == 0) {
            red[(wm * 16 + g) * 2 + wn]     = v0;
            red[(wm * 16 + g + 8) * 2 + wn] = v1;
        }
    }
    __syncthreads();
    if (tid < 128) {
        float iv = 1.0f / (red[tid * 2] + red[tid * 2 + 1]);
        invg[(size_t)bh * Sc + row0 + tid] = iv;
        red2[tid] = iv;
    }
    __syncthreads();

    float* uRed = smf;
    if (wn == 1) {
#pragma unroll
        for (int nt = 0; nt < 8; nt++) {
            int rr = wm * 16 + g, cc = nt * 8 + c * 2;
            uRed[rr * 68 + cc]           = accU[nt][0];
            uRed[rr * 68 + cc + 1]       = accU[nt][1];
            uRed[(rr + 8) * 68 + cc]     = accU[nt][2];
            uRed[(rr + 8) * 68 + cc + 1] = accU[nt][3];
        }
    }
    __syncthreads();
    if (wn == 0) {
        float* cp = ctx + (size_t)(b * Sc + row0) * Dc + h * HDc;
        int rr = wm * 16 + g;
        float iv0 = red2[rr], iv1 = red2[rr + 8];
#pragma unroll
        for (int nt = 0; nt < 8; nt++) {
            int cc = nt * 8 + c * 2;
            float u0 = (accU[nt][0] + uRed[rr * 68 + cc]) * iv0;
            float u1 = (accU[nt][1] + uRed[rr * 68 + cc + 1]) * iv0;
            float u2 = (accU[nt][2] + uRed[(rr + 8) * 68 + cc]) * iv1;
            float u3 = (accU[nt][3] + uRed[(rr + 8) * 68 + cc + 1]) * iv1;
            cp[(size_t)rr * Dc + cc]           = tf32_round(u0);
            cp[(size_t)rr * Dc + cc + 1]       = tf32_round(u1);
            cp[(size_t)(rr + 8) * Dc + cc]     = tf32_round(u2);
            cp[(size_t)(rr + 8) * Dc + cc + 1] = tf32_round(u3);
        }
    }
}

// ============================================================================
// normalize attn in place: attn[row, :] *= inv[row]   (measured 6.55 TB/s)
// ============================================================================
__global__ void norm_k(float4* __restrict__ attn4, const float* __restrict__ inv) {
    const size_t total = (size_t)BHc * Sc * Sc / 4;
    size_t i = (size_t)blockIdx.x * blockDim.x + threadIdx.x;
    const size_t stride = (size_t)gridDim.x * blockDim.x;
    for (; i < total; i += stride) {
        float s = __ldg(&inv[i >> 9]);     // 512 float4 per row
        float4 v = attn4[i];
        v.x *= s; v.y *= s; v.z *= s; v.w *= s;
        attn4[i] = v;
    }
}

// ---------------------------------------------------------------------------
// Side stream + events (host objects created once on the eager first call;
// captured GPU work identical every call).
// ---------------------------------------------------------------------------
static cudaStream_t get_s2() {
    static cudaStream_t s = []{
        cudaStream_t t; cudaStreamCreateWithFlags(&t, cudaStreamNonBlocking); return t;
    }();
    return s;
}
static cudaEvent_t get_ev(int which) {
    static cudaEvent_t e0 = []{
        cudaEvent_t e; cudaEventCreateWithFlags(&e, cudaEventDisableTiming); return e;
    }();
    static cudaEvent_t e1 = []{
        cudaEvent_t e; cudaEventCreateWithFlags(&e, cudaEventDisableTiming); return e;
    }();
    return which == 0 ? e0 : e1;
}

extern "C" void kernel_launch(void* const* d_in, const int* in_sizes, int n_in,
                              void* d_out, int out_size) {
    const float* query = (const float*)d_in[0];
    const float* key   = (const float*)d_in[1];
    const float* value = (const float*)d_in[2];
    const float* Wq = (const float*)d_in[3];
    const float* bq = (const float*)d_in[4];
    const float* Wk = (const float*)d_in[5];
    const float* bk = (const float*)d_in[6];
    const float* Wv = (const float*)d_in[7];
    const float* bv = (const float*)d_in[8];
    const float* Wo = (const float*)d_in[9];
    const float* bo = (const float*)d_in[10];

    float* out = (float*)d_out;
    const size_t OUT_E  = (size_t)Bc * Sc * Dc;
    const size_t ATTN_E = (size_t)BHc * Sc * Sc;

    float* attn;
    if ((size_t)out_size >= OUT_E + ATTN_E) {
        attn = out + OUT_E;
    } else {
        void* p = nullptr; cudaGetSymbolAddress(&p, g_attn_fb); attn = (float*)p;
    }
    float* Qp;   { void* p; cudaGetSymbolAddress(&p, g_Q);      Qp = (float*)p; }
    float* Kp;   { void* p; cudaGetSymbolAddress(&p, g_K);      Kp = (float*)p; }
    float* Vp;   { void* p; cudaGetSymbolAddress(&p, g_V);      Vp = (float*)p; }
    float* Cx;   { void* p; cudaGetSymbolAddress(&p, g_ctx);    Cx = (float*)p; }
    float* isum; { void* p; cudaGetSymbolAddress(&p, g_invsum); isum = (float*)p; }
    float* qin;  { void* p; cudaGetSymbolAddress(&p, g_qin);    qin = (float*)p; }
    float* kin;  { void* p; cudaGetSymbolAddress(&p, g_kin);    kin = (float*)p; }
    float* vin;  { void* p; cudaGetSymbolAddress(&p, g_vin);    vin = (float*)p; }
    float* wq;   { void* p; cudaGetSymbolAddress(&p, g_wq);     wq = (float*)p; }
    float* wk;   { void* p; cudaGetSymbolAddress(&p, g_wk);     wk = (float*)p; }
    float* wv;   { void* p; cudaGetSymbolAddress(&p, g_wv);     wv = (float*)p; }
    float* wo;   { void* p; cudaGetSymbolAddress(&p, g_wo);     wo = (float*)p; }

    cudaFuncSetAttribute(fused_attn, cudaFuncAttributeMaxDynamicSharedMemorySize,
                         FTOT * 4);

    cudaStream_t s2 = get_s2();
    cudaEvent_t evFork = get_ev(0), evJoin = get_ev(1);

    const int M = Bc * Sc;                      // 4096
    dim3 thr(256);

    prep_round<<<dim3(256, 1, 7), thr>>>(
        (const float4*)query, (const float4*)key, (const float4*)value,
        (const float4*)Wq, (const float4*)Wk, (const float4*)Wv, (const float4*)Wo,
        (float4*)qin, (float4*)kin, (float4*)vin,
        (float4*)wq, (float4*)wk, (float4*)wv, (float4*)wo);

    qkv_gemm<<<dim3(Dc / 128, M / 128, 3), thr>>>(qin, kin, vin,
                                                  wq, bq, wk, bk, wv, bv,
                                                  Qp, Kp, Vp);

    dim3 gfa(Sc / 128, BHc);                    // (16, 32)
    fused_attn<<<gfa, dim3(512), FTOT * 4>>>(Qp, Kp, Vp, attn, isum, Cx);

    // fork: out-proj FIRST (fat blocks claim SMs), norm backfills warp slots
    cudaEventRecord(evFork, 0);
    cudaStreamWaitEvent(s2, evFork, 0);

    gemm_bias_tc<<<dim3(Dc / 128, M / 128), thr>>>(Cx, wo, bo, out, M, Dc, Dc);

    norm_k<<<4736, 256, 0, s2>>>((float4*)attn, isum);

    // join: default stream waits for norm before returning
    cudaEventRecord(evJoin, s2);
    cudaStreamWaitEvent(0, evJoin, 0);
}

// round 14
// speedup vs baseline: 1.1020x; 1.0562x over previous
#include <cuda_runtime.h>
#include <cstdint>

#define Bc 2
#define Sc 2048
#define Dc 1024
#define Hc 16
#define HDc 64
#define BHc (Bc*Hc)
#define SCALEc 0.125f              // 64^-0.5
#define KLOG2 0.1803368801111243f // SCALEc * log2(e)

// ---- scratch (allocation-free rule: __device__ globals) --------------------
__device__ float g_Q[(size_t)Bc * Sc * Dc];
__device__ float g_K[(size_t)Bc * Sc * Dc];
__device__ float g_V[(size_t)Bc * Sc * Dc];
__device__ float g_ctx[(size_t)Bc * Sc * Dc];
__device__ float g_invsum[(size_t)BHc * Sc];
// pre-rounded (tf32) copies of inputs + weights
__device__ float g_qin[(size_t)Bc * Sc * Dc];
__device__ float g_kin[(size_t)Bc * Sc * Dc];
__device__ float g_vin[(size_t)Bc * Sc * Dc];
__device__ float g_wq[(size_t)Dc * Dc];
__device__ float g_wk[(size_t)Dc * Dc];
__device__ float g_wv[(size_t)Dc * Dc];
__device__ float g_wo[(size_t)Dc * Dc];
__device__ float g_attn_fb[(size_t)BHc * Sc * Sc];   // fallback if out only holds `output`

// ---- helpers ----------------------------------------------------------------
__device__ __forceinline__ float tf32_round(float x) {
    return __uint_as_float((__float_as_uint(x) + 0x1000u) & 0xFFFFE000u);
}
__device__ __forceinline__ uint32_t f2tf(float x) {
    uint32_t r; asm("cvt.rna.tf32.f32 %0, %1;" : "=r"(r) : "f"(x)); return r;
}
__device__ __forceinline__ float ex2(float x) {
    float r; asm("ex2.approx.f32 %0, %1;" : "=f"(r) : "f"(x)); return r;
}
__device__ __forceinline__ void mma8(float* d, const uint32_t* a, const uint32_t* b) {
    asm volatile(
        "mma.sync.aligned.m16n8k8.row.col.f32.tf32.tf32.f32 "
        "{%0,%1,%2,%3}, {%4,%5,%6,%7}, {%8,%9}, {%0,%1,%2,%3};\n"
        : "+f"(d[0]), "+f"(d[1]), "+f"(d[2]), "+f"(d[3])
        : "r"(a[0]), "r"(a[1]), "r"(a[2]), "r"(a[3]), "r"(b[0]), "r"(b[1]));
}
__device__ __forceinline__ uint32_t smem_u32(const void* p) {
    uint32_t r;
    asm("{ .reg .u64 t; cvta.to.shared.u64 t, %1; cvt.u32.u64 %0, t; }"
        : "=r"(r) : "l"(p));
    return r;
}
__device__ __forceinline__ void cpa16(uint32_t saddr, const void* g) {
    asm volatile("cp.async.cg.shared.global [%0], [%1], 16;" :: "r"(saddr), "l"(g));
}
__device__ __forceinline__ void cpa_commit() { asm volatile("cp.async.commit_group;"); }
__device__ __forceinline__ void cpa_wait0()  { asm volatile("cp.async.wait_group 0;"); }
__device__ __forceinline__ void cpa_wait1()  { asm volatile("cp.async.wait_group 1;"); }

// ============================================================================
// prep: round inputs + weights to tf32 (producer-side rounding).
// ============================================================================
__global__ __launch_bounds__(256)
void prep_round(const float4* __restrict__ q, const float4* __restrict__ k,
                const float4* __restrict__ v,
                const float4* __restrict__ wq, const float4* __restrict__ wk,
                const float4* __restrict__ wv, const float4* __restrict__ wo,
                float4* __restrict__ oq, float4* __restrict__ ok,
                float4* __restrict__ ov,
                float4* __restrict__ owq, float4* __restrict__ owk,
                float4* __restrict__ owv, float4* __restrict__ owo) {
    const float4* src; float4* dst; size_t n4;
    const size_t NIN = (size_t)Bc * Sc * Dc / 4;
    const size_t NW  = (size_t)Dc * Dc / 4;
    switch (blockIdx.z) {
        case 0: src = q;  dst = oq;  n4 = NIN; break;
        case 1: src = k;  dst = ok;  n4 = NIN; break;
        case 2: src = v;  dst = ov;  n4 = NIN; break;
        case 3: src = wq; dst = owq; n4 = NW;  break;
        case 4: src = wk; dst = owk; n4 = NW;  break;
        case 5: src = wv; dst = owv; n4 = NW;  break;
        default: src = wo; dst = owo; n4 = NW;  break;
    }
    size_t i = (size_t)blockIdx.x * 256 + threadIdx.x;
    const size_t stride = (size_t)gridDim.x * 256;
    for (; i < n4; i += stride) {
        float4 t = src[i];
        t.x = tf32_round(t.x); t.y = tf32_round(t.y);
        t.z = tf32_round(t.z); t.w = tf32_round(t.w);
        dst[i] = t;
    }
}

// ============================================================================
// GEMM + bias: cp.async double-buffered, BK=16, pure-truncation tf32
// fragments (operands pre-rounded, so truncation == rna).
// ============================================================================
struct GemmSmem {
    float As[2][128][20];
    float Bs[2][16][136];
};

template<bool RND_OUT>
__device__ __forceinline__
void gemm_body(const float* __restrict__ A, const float* __restrict__ W,
               const float* __restrict__ bias, float* __restrict__ C,
               int M, int N, int K, GemmSmem& sm) {
    const int tid = threadIdx.x;
    const int lane = tid & 31, warp = tid >> 5;
    const int wm = warp >> 2, wn = warp & 3;
    const int row0 = blockIdx.y * 128, col0 = blockIdx.x * 128;
    const int r_lo = lane >> 2, c_lo = lane & 3;

    const int rowA = tid >> 1, colA = (tid & 1) * 8;
    const int rowB = tid >> 4, colB = (tid & 15) * 8;

    const uint32_t sA[2] = { smem_u32(&sm.As[0][rowA][colA]),
                             smem_u32(&sm.As[1][rowA][colA]) };
    const uint32_t sB[2] = { smem_u32(&sm.Bs[0][rowB][colB]),
                             smem_u32(&sm.Bs[1][rowB][colB]) };
    const float* gA = A + (size_t)(row0 + rowA) * K + colA;
    const float* gB = W + (size_t)rowB * N + col0 + colB;

    float acc[4][4][4] = {};

    cpa16(sA[0], gA); cpa16(sA[0] + 16, gA + 4);
    cpa16(sB[0], gB); cpa16(sB[0] + 16, gB + 4);
    cpa_commit();

    const int nk = K >> 4;
    for (int kt = 0; kt < nk; kt++) {
        const int s = kt & 1;
        if (kt + 1 < nk) {
            const float* gA2 = gA + (kt + 1) * 16;
            const float* gB2 = gB + (size_t)(kt + 1) * 16 * N;
            cpa16(sA[s ^ 1], gA2); cpa16(sA[s ^ 1] + 16, gA2 + 4);
            cpa16(sB[s ^ 1], gB2); cpa16(sB[s ^ 1] + 16, gB2 + 4);
            cpa_commit();
            cpa_wait1();
        } else {
            cpa_wait0();
        }
        __syncthreads();

        const float (*As_)[20]  = sm.As[s];
        const float (*Bs_)[136] = sm.Bs[s];
#pragma unroll
        for (int ks = 0; ks < 16; ks += 8) {
            uint32_t af[4][4], bf[4][2];
#pragma unroll
            for (int mt = 0; mt < 4; mt++) {
                int rb = wm * 64 + mt * 16 + r_lo;
                af[mt][0] = __float_as_uint(As_[rb][ks + c_lo]);
                af[mt][1] = __float_as_uint(As_[rb + 8][ks + c_lo]);
                af[mt][2] = __float_as_uint(As_[rb][ks + 4 + c_lo]);
                af[mt][3] = __float_as_uint(As_[rb + 8][ks + 4 + c_lo]);
            }
#pragma unroll
            for (int nt = 0; nt < 4; nt++) {
                int cb = wn * 32 + nt * 8 + r_lo;
                bf[nt][0] = __float_as_uint(Bs_[ks + c_lo][cb]);
                bf[nt][1] = __float_as_uint(Bs_[ks + 4 + c_lo][cb]);
            }
#pragma unroll
            for (int mt = 0; mt < 4; mt++)
#pragma unroll
                for (int nt = 0; nt < 4; nt++)
                    mma8(acc[mt][nt], af[mt], bf[nt]);
        }
        __syncthreads();
    }

#pragma unroll
    for (int mt = 0; mt < 4; mt++) {
        int row = row0 + wm * 64 + mt * 16 + r_lo;
#pragma unroll
        for (int nt = 0; nt < 4; nt++) {
            int col = col0 + wn * 32 + nt * 8 + c_lo * 2;
            float b0 = bias[col], b1 = bias[col + 1];
            float v0 = acc[mt][nt][0] + b0, v1 = acc[mt][nt][1] + b1;
            float v2 = acc[mt][nt][2] + b0, v3 = acc[mt][nt][3] + b1;
            if (RND_OUT) {
                v0 = tf32_round(v0); v1 = tf32_round(v1);
                v2 = tf32_round(v2); v3 = tf32_round(v3);
            }
            C[(size_t)row * N + col]           = v0;
            C[(size_t)row * N + col + 1]       = v1;
            C[(size_t)(row + 8) * N + col]     = v2;
            C[(size_t)(row + 8) * N + col + 1] = v3;
        }
    }
}

__global__ __launch_bounds__(256)
void gemm_bias_tc(const float* __restrict__ A, const float* __restrict__ W,
                  const float* __restrict__ bias, float* __restrict__ C,
                  int M, int N, int K) {
    __shared__ GemmSmem sm;
    gemm_body<false>(A, W, bias, C, M, N, K, sm);
}

__global__ __launch_bounds__(256)
void qkv_gemm(const float* __restrict__ q, const float* __restrict__ k,
              const float* __restrict__ v,
              const float* __restrict__ Wq, const float* __restrict__ bq,
              const float* __restrict__ Wk, const float* __restrict__ bk,
              const float* __restrict__ Wv, const float* __restrict__ bv,
              float* __restrict__ Qo, float* __restrict__ Ko, float* __restrict__ Vo) {
    __shared__ GemmSmem sm;
    const float *A, *W, *bias; float* C;
    if (blockIdx.z == 0)      { A = q; W = Wq; bias = bq; C = Qo; }
    else if (blockIdx.z == 1) { A = k; W = Wk; bias = bk; C = Ko; }
    else                      { A = v; W = Wv; bias = bv; C = Vo; }
    gemm_body<true>(A, W, bias, C, Bc * Sc, Dc, Dc, sm);
}

// ============================================================================
// Fused attention — round-10 config + bh_base for half-grid pipelining.
// 512 threads (16 warps, 8m x 2n), 128 q-rows/block, double-buffered K/V.
// ============================================================================
#define FK0 0
#define FK1 8704
#define FV0 17408
#define FV1 26112
#define FRED 34816
#define FRED2 35072
#define FTOT 35200            // *4 = 140800 bytes

__global__ __launch_bounds__(512)
void fused_attn(const float* __restrict__ Qp, const float* __restrict__ Kp,
                const float* __restrict__ Vp, float* __restrict__ attn,
                float* __restrict__ invg, float* __restrict__ ctx, int bh_base) {
    extern __shared__ float smf[];
    const uint32_t sbase = smem_u32(smf);

    const int bh = bh_base + blockIdx.y, b = bh >> 4, h = bh & 15;
    const int row0 = blockIdx.x * 128;
    const float* Qh = Qp + (size_t)b * Sc * Dc + h * HDc;
    const float* Kh = Kp + (size_t)b * Sc * Dc + h * HDc;
    const float* Vh = Vp + (size_t)b * Sc * Dc + h * HDc;
    float* outp = attn + (size_t)bh * Sc * Sc;

    const int tid = threadIdx.x, lane = tid & 31, warp = tid >> 5;
    const int wm = warp >> 1, wn = warp & 1;   // 8m x 2n
    const int g = lane >> 2, c = lane & 3;

    const int ldr0 = tid >> 4;                 // rows 0..31 (+32 per i)
    const int ldc4 = (tid & 15) * 4;

    {
#pragma unroll
        for (int i = 0; i < 4; i++) {
            int r = ldr0 + i * 32;
            cpa16(sbase + (uint32_t)(FK0 + r * 68 + ldc4) * 4, Kh + (size_t)r * Dc + ldc4);
            cpa16(sbase + (uint32_t)(FV0 + r * 68 + ldc4) * 4, Vh + (size_t)r * Dc + ldc4);
        }
        cpa_commit();
    }

    // Q fragments: raw bits (Qp pre-rounded to tf32 by qkv epilogue)
    uint32_t qf[8][4];
    {
        const int qr = row0 + wm * 16;
#pragma unroll
        for (int s8 = 0; s8 < 8; s8++) {
            qf[s8][0] = __float_as_uint(Qh[(size_t)(qr + g)     * Dc + s8 * 8 + c]);
            qf[s8][1] = __float_as_uint(Qh[(size_t)(qr + g + 8) * Dc + s8 * 8 + c]);
            qf[s8][2] = __float_as_uint(Qh[(size_t)(qr + g)     * Dc + s8 * 8 + c + 4]);
            qf[s8][3] = __float_as_uint(Qh[(size_t)(qr + g + 8) * Dc + s8 * 8 + c + 4]);
        }
    }

    cpa_wait0();
    __syncthreads();

    float accU[8][4] = {};
    float rs0 = 0.f, rs1 = 0.f;

    const int src1 = (lane & ~3) | (c >> 1);
    const int src2 = src1 + 2;
    const bool odd = (c & 1);

    for (int kt = 0; kt < 16; kt++) {
        const int s = kt & 1;
        if (kt + 1 < 16) {
            const float* gk = Kh + (size_t)((kt + 1) * 128) * Dc;
            const float* gv = Vh + (size_t)((kt + 1) * 128) * Dc;
            const int KD = s ? FK0 : FK1;
            const int VD = s ? FV0 : FV1;
#pragma unroll
            for (int i = 0; i < 4; i++) {
                int r = ldr0 + i * 32;
                cpa16(sbase + (uint32_t)(KD + r * 68 + ldc4) * 4, gk + (size_t)r * Dc + ldc4);
                cpa16(sbase + (uint32_t)(VD + r * 68 + ldc4) * 4, gv + (size_t)r * Dc + ldc4);
            }
            cpa_commit();
        }
        const float* sK = smf + (s ? FK1 : FK0);
        const float* sV = smf + (s ? FV1 : FV0);
        const int k0 = kt * 128;

#pragma unroll
        for (int half = 0; half < 2; half++) {
            const int colbase = wn * 64 + half * 32;

            float accS[4][4] = {};
#pragma unroll
            for (int s8 = 0; s8 < 8; s8++) {
                uint32_t bf[4][2];
#pragma unroll
                for (int nt = 0; nt < 4; nt++) {
                    int kc = colbase + nt * 8 + g;
                    bf[nt][0] = __float_as_uint(sK[kc * 68 + s8 * 8 + c]);
                    bf[nt][1] = __float_as_uint(sK[kc * 68 + s8 * 8 + c + 4]);
                }
#pragma unroll
                for (int nt = 0; nt < 4; nt++)
                    mma8(accS[nt], qf[s8], bf[nt]);
            }

            const int grow = row0 + wm * 16 + g;
#pragma unroll
            for (int nt = 0; nt < 4; nt++) {
                float e0 = ex2(accS[nt][0] * KLOG2);
                float e1 = ex2(accS[nt][1] * KLOG2);
                float e2 = ex2(accS[nt][2] * KLOG2);
                float e3 = ex2(accS[nt][3] * KLOG2);
                rs0 += e0 + e1; rs1 += e2 + e3;
                int gcol = k0 + colbase + nt * 8 + c * 2;
                *reinterpret_cast<float2*>(&outp[(size_t)grow * Sc + gcol])       = make_float2(e0, e1);
                *reinterpret_cast<float2*>(&outp[(size_t)(grow + 8) * Sc + gcol]) = make_float2(e2, e3);
                accS[nt][0] = e0; accS[nt][1] = e1; accS[nt][2] = e2; accS[nt][3] = e3;
            }

#pragma unroll
            for (int s4 = 0; s4 < 4; s4++) {
                float x0 = __shfl_sync(0xffffffffu, accS[s4][0], src1);
                float x1 = __shfl_sync(0xffffffffu, accS[s4][1], src1);
                float y0 = __shfl_sync(0xffffffffu, accS[s4][2], src1);
                float y1 = __shfl_sync(0xffffffffu, accS[s4][3], src1);
                float z0 = __shfl_sync(0xffffffffu, accS[s4][0], src2);
                float z1 = __shfl_sync(0xffffffffu, accS[s4][1], src2);
                float w0 = __shfl_sync(0xffffffffu, accS[s4][2], src2);
                float w1 = __shfl_sync(0xffffffffu, accS[s4][3], src2);
                uint32_t af[4];
                af[0] = f2tf(odd ? x1 : x0);
                af[1] = f2tf(odd ? y1 : y0);
                af[2] = f2tf(odd ? z1 : z0);
                af[3] = f2tf(odd ? w1 : w0);
                const int vr = colbase + s4 * 8 + c;
#pragma unroll
                for (int nt = 0; nt < 8; nt++) {
                    uint32_t bf[2];
                    bf[0] = __float_as_uint(sV[vr * 68 + nt * 8 + g]);
                    bf[1] = __float_as_uint(sV[(vr + 4) * 68 + nt * 8 + g]);
                    mma8(accU[nt], af, bf);
                }
            }
        }

        if (kt + 1 < 16) cpa_wait0();
        __syncthreads();
    }

    float* red  = smf + FRED;
    float* red2 = smf + FRED2;
    {
        float v0 = rs0, v1 = rs1;
        v0 += __shfl_xor_sync(0xffffffffu, v0, 1);
        v0 += __shfl_xor_sync(0xffffffffu, v0, 2);
        v1 += __shfl_xor_sync(0xffffffffu, v1, 1);
        v1 += __shfl_xor_sync(0xffffffffu, v1, 2);
        if (c == 0) {
            red[(wm * 16 + g) * 2 + wn]     = v0;
            red[(wm * 16 + g + 8) * 2 + wn] = v1;
        }
    }
    __syncthreads();
    if (tid < 128) {
        float iv = 1.0f / (red[tid * 2] + red[tid * 2 + 1]);
        invg[(size_t)bh * Sc + row0 + tid] = iv;
        red2[tid] = iv;
    }
    __syncthreads();

    float* uRed = smf;
    if (wn == 1) {
#pragma unroll
        for (int nt = 0; nt < 8; nt++) {
            int rr = wm * 16 + g, cc = nt * 8 + c * 2;
            uRed[rr * 68 + cc]           = accU[nt][0];
            uRed[rr * 68 + cc + 1]       = accU[nt][1];
            uRed[(rr + 8) * 68 + cc]     = accU[nt][2];
            uRed[(rr + 8) * 68 + cc + 1] = accU[nt][3];
        }
    }
    __syncthreads();
    if (wn == 0) {
        float* cp = ctx + (size_t)(b * Sc + row0) * Dc + h * HDc;
        int rr = wm * 16 + g;
        float iv0 = red2[rr], iv1 = red2[rr + 8];
#pragma unroll
        for (int nt = 0; nt < 8; nt++) {
            int cc = nt * 8 + c * 2;
            float u0 = (accU[nt][0] + uRed[rr * 68 + cc]) * iv0;
            float u1 = (accU[nt][1] + uRed[rr * 68 + cc + 1]) * iv0;
            float u2 = (accU[nt][2] + uRed[(rr + 8) * 68 + cc]) * iv1;
            float u3 = (accU[nt][3] + uRed[(rr + 8) * 68 + cc + 1]) * iv1;
            cp[(size_t)rr * Dc + cc]           = tf32_round(u0);
            cp[(size_t)rr * Dc + cc + 1]       = tf32_round(u1);
            cp[(size_t)(rr + 8) * Dc + cc]     = tf32_round(u2);
            cp[(size_t)(rr + 8) * Dc + cc + 1] = tf32_round(u3);
        }
    }
}

// ============================================================================
// normalize a range of attn in place: attn[row, :] *= inv[row]
// base4/n4 are float4-granular; row = global_float4_index >> 9.
// ============================================================================
__global__ void norm_k(float4* __restrict__ attn4, const float* __restrict__ inv,
                       size_t base4, size_t n4) {
    size_t i = (size_t)blockIdx.x * blockDim.x + threadIdx.x;
    const size_t stride = (size_t)gridDim.x * blockDim.x;
    for (; i < n4; i += stride) {
        size_t idx = base4 + i;
        float s = __ldg(&inv[idx >> 9]);   // 512 float4 per row
        float4 v = attn4[idx];
        v.x *= s; v.y *= s; v.z *= s; v.w *= s;
        attn4[idx] = v;
    }
}

// ---------------------------------------------------------------------------
// Side stream + events (host objects created once on the eager first call;
// captured GPU work identical every call).
// ---------------------------------------------------------------------------
static cudaStream_t get_s2() {
    static cudaStream_t s = []{
        cudaStream_t t; cudaStreamCreateWithFlags(&t, cudaStreamNonBlocking); return t;
    }();
    return s;
}
static cudaEvent_t get_ev(int which) {
    static cudaEvent_t ev[3] = { nullptr, nullptr, nullptr };
    static bool init = []{
        for (int i = 0; i < 3; i++)
            cudaEventCreateWithFlags(&ev[i], cudaEventDisableTiming);
        return true;
    }();
    (void)init;
    return ev[which];
}

extern "C" void kernel_launch(void* const* d_in, const int* in_sizes, int n_in,
                              void* d_out, int out_size) {
    const float* query = (const float*)d_in[0];
    const float* key   = (const float*)d_in[1];
    const float* value = (const float*)d_in[2];
    const float* Wq = (const float*)d_in[3];
    const float* bq = (const float*)d_in[4];
    const float* Wk = (const float*)d_in[5];
    const float* bk = (const float*)d_in[6];
    const float* Wv = (const float*)d_in[7];
    const float* bv = (const float*)d_in[8];
    const float* Wo = (const float*)d_in[9];
    const float* bo = (const float*)d_in[10];

    float* out = (float*)d_out;
    const size_t OUT_E  = (size_t)Bc * Sc * Dc;
    const size_t ATTN_E = (size_t)BHc * Sc * Sc;

    float* attn;
    if ((size_t)out_size >= OUT_E + ATTN_E) {
        attn = out + OUT_E;
    } else {
        void* p = nullptr; cudaGetSymbolAddress(&p, g_attn_fb); attn = (float*)p;
    }
    float* Qp;   { void* p; cudaGetSymbolAddress(&p, g_Q);      Qp = (float*)p; }
    float* Kp;   { void* p; cudaGetSymbolAddress(&p, g_K);      Kp = (float*)p; }
    float* Vp;   { void* p; cudaGetSymbolAddress(&p, g_V);      Vp = (float*)p; }
    float* Cx;   { void* p; cudaGetSymbolAddress(&p, g_ctx);    Cx = (float*)p; }
    float* isum; { void* p; cudaGetSymbolAddress(&p, g_invsum); isum = (float*)p; }
    float* qin;  { void* p; cudaGetSymbolAddress(&p, g_qin);    qin = (float*)p; }
    float* kin;  { void* p; cudaGetSymbolAddress(&p, g_kin);    kin = (float*)p; }
    float* vin;  { void* p; cudaGetSymbolAddress(&p, g_vin);    vin = (float*)p; }
    float* wq;   { void* p; cudaGetSymbolAddress(&p, g_wq);     wq = (float*)p; }
    float* wk;   { void* p; cudaGetSymbolAddress(&p, g_wk);     wk = (float*)p; }
    float* wv;   { void* p; cudaGetSymbolAddress(&p, g_wv);     wv = (float*)p; }
    float* wo;   { void* p; cudaGetSymbolAddress(&p, g_wo);     wo = (float*)p; }

    cudaFuncSetAttribute(fused_attn, cudaFuncAttributeMaxDynamicSharedMemorySize,
                         FTOT * 4);

    cudaStream_t s2 = get_s2();
    cudaEvent_t evA = get_ev(0), evB = get_ev(1), evJoin = get_ev(2);

    const int M = Bc * Sc;                      // 4096
    dim3 thr(256);
    const size_t HALF4 = ATTN_E / 8;            // half of attn in float4 units

    prep_round<<<dim3(256, 1, 7), thr>>>(
        (const float4*)query, (const float4*)key, (const float4*)value,
        (const float4*)Wq, (const float4*)Wk, (const float4*)Wv, (const float4*)Wo,
        (float4*)qin, (float4*)kin, (float4*)vin,
        (float4*)wq, (float4*)wk, (float4*)wv, (float4*)wo);

    qkv_gemm<<<dim3(Dc / 128, M / 128, 3), thr>>>(qin, kin, vin,
                                                  wq, bq, wk, bk, wv, bv,
                                                  Qp, Kp, Vp);

    // ---- fused attention split into two half-grids (bh 0..15, 16..31) ----
    dim3 gfa(Sc / 128, BHc / 2);                // (16, 16)

    fused_attn<<<gfa, dim3(512), FTOT * 4>>>(Qp, Kp, Vp, attn, isum, Cx, 0);
    cudaEventRecord(evA, 0);

    fused_attn<<<gfa, dim3(512), FTOT * 4>>>(Qp, Kp, Vp, attn, isum, Cx, BHc / 2);
    cudaEventRecord(evB, 0);

    // s2: norm first half while second half of fused runs on s0
    cudaStreamWaitEvent(s2, evA, 0);
    norm_k<<<2368, 256, 0, s2>>>((float4*)attn, isum, 0, HALF4);

    // out-projection on s0 (fat blocks claim SMs first)
    gemm_bias_tc<<<dim3(Dc / 128, M / 128), thr>>>(Cx, wo, bo, out, M, Dc, Dc);

    // s2: norm second half (after fused_B), overlapping out-proj
    cudaStreamWaitEvent(s2, evB, 0);
    norm_k<<<2368, 256, 0, s2>>>((float4*)attn, isum, HALF4, HALF4);

    // join
    cudaEventRecord(evJoin, s2);
    cudaStreamWaitEvent(0, evJoin, 0);
}